// round 4
// baseline (speedup 1.0000x reference)
#include <cuda_runtime.h>
#include <cstdint>
#include <math.h>

#define BBAT 2
#define LL   2048
#define DD   1024
#define HH   16
#define DHD  64
#define DFFN 4096
#define MTOT (BBAT*LL)   // 4096

// ---- scratch (__device__ globals; no allocation allowed) ----
__device__ float g_qkv  [(size_t)MTOT*3*DD];
__device__ float g_attn [(size_t)MTOT*DD];
__device__ float g_t0   [(size_t)MTOT*DD];
__device__ float g_h1   [(size_t)MTOT*DD];
__device__ float g_h1r  [(size_t)MTOT*DD];
__device__ float g_ffn  [(size_t)MTOT*DFFN];
__device__ float g_xr   [(size_t)MTOT*DD];
__device__ float g_wqkvr[(size_t)3*DD*DD];
__device__ float g_wor  [(size_t)DD*DD];
__device__ float g_w1r  [(size_t)DFFN*DD];
__device__ float g_w2r  [(size_t)DD*DFFN];

// ============================================================
// Helpers
// ============================================================
__device__ __forceinline__ float rnatf32(float x) {
    uint32_t r; asm("cvt.rna.tf32.f32 %0, %1;" : "=r"(r) : "f"(x));
    return __uint_as_float(r);
}
__device__ __forceinline__ void mma8(float* c, uint32_t a0, uint32_t a1,
                                     uint32_t a2, uint32_t a3,
                                     uint32_t b0, uint32_t b1) {
    asm volatile(
        "mma.sync.aligned.m16n8k8.row.col.f32.tf32.tf32.f32 "
        "{%0,%1,%2,%3}, {%4,%5,%6,%7}, {%8,%9}, {%0,%1,%2,%3};\n"
        : "+f"(c[0]), "+f"(c[1]), "+f"(c[2]), "+f"(c[3])
        : "r"(a0), "r"(a1), "r"(a2), "r"(a3), "r"(b0), "r"(b1));
}
__device__ __forceinline__ void cp_async16(uint32_t dst, const void* src) {
    asm volatile("cp.async.cg.shared.global [%0], [%1], 16;\n" :: "r"(dst), "l"(src));
}
__device__ __forceinline__ void cp_commit() { asm volatile("cp.async.commit_group;\n"); }
template<int N> __device__ __forceinline__ void cp_wait() {
    asm volatile("cp.async.wait_group %0;\n" :: "n"(N));
}
__device__ __forceinline__ uint64_t ffma2(uint64_t a, uint64_t b, uint64_t c) {
    uint64_t d;
    asm("fma.rn.f32x2 %0, %1, %2, %3;" : "=l"(d) : "l"(a), "l"(b), "l"(c));
    return d;
}
// permuted position of element k within its 8-group (pairs (k,k+4) adjacent)
__device__ __forceinline__ int pidx(int d) {
    return (d & ~7) + 2 * (d & 3) + ((d >> 2) & 1);
}

// ============================================================
// round+permute: out groups of 8 stored as [k0,k4,k1,k5,k2,k6,k3,k7], rna-tf32
// ============================================================
__global__ void __launch_bounds__(256) round_perm_kernel(
    const float* __restrict__ in, float* __restrict__ out, int n8)
{
    int i = blockIdx.x * 256 + threadIdx.x;
    if (i < n8) {
        float4 a = *(const float4*)&in[(size_t)i * 8];
        float4 b = *(const float4*)&in[(size_t)i * 8 + 4];
        float4 o1, o2;
        o1.x = rnatf32(a.x); o1.y = rnatf32(b.x); o1.z = rnatf32(a.y); o1.w = rnatf32(b.y);
        o2.x = rnatf32(a.z); o2.y = rnatf32(b.z); o2.z = rnatf32(a.w); o2.w = rnatf32(b.w);
        *(float4*)&out[(size_t)i * 8]     = o1;
        *(float4*)&out[(size_t)i * 8 + 4] = o2;
    }
}

// ============================================================
// TF32 mma.sync GEMM on pre-permuted operands.
// C[M,N] = A[M,K] @ W[N,K]^T + bias (+res)(relu)(perm+round out)
// Block 128 x BN_, BK=32, 8 warps (2x4), warp tile 64 x (BN_/4).
// Smem: A/W rows of 32 floats, k-group XOR-swizzled by (row&3);
// fragments load as conflict-free LDS.64. 4-slot cp.async ring.
// ============================================================
#define BK 32
#define NSLOT 4

template<int BN_, bool RELU, bool RES, bool PERM>
__global__ void __launch_bounds__(256, 1) gemm_mma(
    const float* __restrict__ A, const float* __restrict__ W,
    const float* __restrict__ bias, const float* __restrict__ res,
    float* __restrict__ C, int M, int N, int K)
{
    constexpr int NI = BN_ / 32;              // B fragments per warp per ks
    constexpr int STAGE_F = (128 + BN_) * BK; // floats per stage
    extern __shared__ float smemf[];
    const uint32_t sbase = (uint32_t)__cvta_generic_to_shared(smemf);

    const int tid = threadIdx.x;
    const int lane = tid & 31, wid = tid >> 5;
    const int bm = blockIdx.y * 128, bn = blockIdx.x * BN_;
    const int wm = (wid >> 2) * 64;
    const int wn = (wid & 3) * (BN_ / 4);
    const int gid = lane >> 2, tig = lane & 3;
    const int T = K / BK;

    float acc[4][NI][4];
#pragma unroll
    for (int mi = 0; mi < 4; mi++)
#pragma unroll
        for (int ni = 0; ni < NI; ni++)
#pragma unroll
            for (int r = 0; r < 4; r++) acc[mi][ni][r] = 0.f;

    auto load_tile = [&](int t) {
        const uint32_t st = sbase + (uint32_t)(t & 3) * (STAGE_F * 4);
        const int kt = t * BK;
#pragma unroll
        for (int i = 0; i < 4; i++) {           // A: 1024 chunks of 16B
            int c = tid + i * 256;
            int r = c >> 3, h = c & 7;
            uint32_t dst = st + (uint32_t)(r * 128 + (((h >> 1) ^ (r & 3)) * 32) + (h & 1) * 16);
            cp_async16(dst, A + (size_t)(bm + r) * K + kt + h * 4);
        }
        const uint32_t stb = st + 128 * BK * 4;
#pragma unroll
        for (int i = 0; i < BN_ / 32; i++) {    // B: BN_*8 chunks
            int c = tid + i * 256;
            int r = c >> 3, h = c & 7;
            uint32_t dst = stb + (uint32_t)(r * 128 + (((h >> 1) ^ (r & 3)) * 32) + (h & 1) * 16);
            cp_async16(dst, W + (size_t)(bn + r) * K + kt + h * 4);
        }
    };

    load_tile(0); cp_commit();
    load_tile(1); cp_commit();

    for (int t = 0; t < T; t++) {
        if (t + 2 < T) load_tile(t + 2);
        cp_commit();
        cp_wait<2>();
        __syncthreads();

        const float* Ab = smemf + (size_t)(t & 3) * STAGE_F;
        const float* Bb = Ab + 128 * BK;
#pragma unroll
        for (int ks = 0; ks < 4; ks++) {
            const int sw = (ks ^ (gid & 3)) * 8 + tig * 2;
            float2 fa[4][2];
#pragma unroll
            for (int mi = 0; mi < 4; mi++) {
                const float* p = Ab + (wm + mi * 16 + gid) * 32 + sw;
                fa[mi][0] = *(const float2*)p;
                fa[mi][1] = *(const float2*)(p + 8 * 32);
            }
            float2 fb[NI];
#pragma unroll
            for (int ni = 0; ni < NI; ni++) {
                const float* p = Bb + (wn + ni * 8 + gid) * 32 + sw;
                fb[ni] = *(const float2*)p;
            }
#pragma unroll
            for (int mi = 0; mi < 4; mi++)
#pragma unroll
                for (int ni = 0; ni < NI; ni++)
                    mma8(acc[mi][ni],
                         __float_as_uint(fa[mi][0].x), __float_as_uint(fa[mi][1].x),
                         __float_as_uint(fa[mi][0].y), __float_as_uint(fa[mi][1].y),
                         __float_as_uint(fb[ni].x),    __float_as_uint(fb[ni].y));
        }
        __syncthreads();
    }

    // epilogue
#pragma unroll
    for (int ni = 0; ni < NI; ni++) {
        const int cb = bn + wn + ni * 8;
        const int c0 = 2 * tig, c1 = 2 * tig + 1;
        const float b0 = bias[cb + c0], b1 = bias[cb + c1];
#pragma unroll
        for (int mi = 0; mi < 4; mi++) {
            const int row = bm + wm + mi * 16 + gid;
#pragma unroll
            for (int rr = 0; rr < 2; rr++) {
                const int r = row + rr * 8;
                float v0 = acc[mi][ni][rr * 2 + 0] + b0;
                float v1 = acc[mi][ni][rr * 2 + 1] + b1;
                size_t off = (size_t)r * N + cb + c0;
                if (RES) { v0 += res[off]; v1 += res[off + 1]; }
                if (RELU) { v0 = fmaxf(v0, 0.f); v1 = fmaxf(v1, 0.f); }
                if (PERM) {
                    C[(size_t)r * N + cb + pidx(c0)] = rnatf32(v0);
                    C[(size_t)r * N + cb + pidx(c1)] = rnatf32(v1);
                } else {
                    float2 o; o.x = v0; o.y = v1;
                    *(float2*)&C[off] = o;
                }
            }
        }
    }
}

// ============================================================
// Causal flash attention, fp32 + f32x2 QK. Output permuted+tf32-rounded.
// ============================================================
#define PADQ 68
#define PADP 36
union F4U2 { float4 f4; uint64_t u2[2]; };

__global__ void __launch_bounds__(256) attn_kernel(
    const float* __restrict__ qkv, float* __restrict__ O)
{
    __shared__ float Qs[64 * PADQ];
    __shared__ float Ks[32 * PADQ];
    __shared__ float Vs[32 * PADQ];
    __shared__ float Ps[64 * PADP];

    const int qi = blockIdx.x, h = blockIdx.y, b = blockIdx.z;
    const int tid = threadIdx.x, lane = tid & 31, wid = tid >> 5;
    const size_t qbase = (size_t)b * LL * 3 * DD + (size_t)h * DHD;

#pragma unroll
    for (int i = 0; i < 4; i++) {
        int f = i * 256 + tid;
        int r = f >> 4, d4 = f & 15;
        float4 v = *(const float4*)&qkv[qbase + (size_t)(qi*64 + r) * 3072 + d4*4];
        *(float4*)&Qs[r * PADQ + d4 * 4] = v;
    }

    float m[8], lsum[8], acc0[8], acc1[8];
#pragma unroll
    for (int i = 0; i < 8; i++) { m[i] = -1e30f; lsum[i] = 0.f; acc0[i] = 0.f; acc1[i] = 0.f; }

    const int ktmax = 2 * qi + 1;
    for (int kt = 0; kt <= ktmax; kt++) {
        __syncthreads();
#pragma unroll
        for (int i = 0; i < 2; i++) {
            int f = i * 256 + tid;
            int r = f >> 4, d4 = f & 15;
            size_t grow = qbase + (size_t)(kt*32 + r) * 3072 + d4*4;
            *(float4*)&Ks[r * PADQ + d4*4] = *(const float4*)&qkv[grow + 1024];
            *(float4*)&Vs[r * PADQ + d4*4] = *(const float4*)&qkv[grow + 2048];
        }
        __syncthreads();

        // S = Q K^T, packed f32x2 accumulation
        uint64_t s2[8];
#pragma unroll
        for (int i = 0; i < 8; i++) s2[i] = 0ull;
#pragma unroll
        for (int d4 = 0; d4 < 16; d4++) {
            F4U2 k; k.f4 = *(const float4*)&Ks[lane * PADQ + d4*4];
#pragma unroll
            for (int i = 0; i < 8; i++) {
                F4U2 q; q.f4 = *(const float4*)&Qs[(wid*8 + i) * PADQ + d4*4];
                s2[i] = ffma2(q.u2[0], k.u2[0], s2[i]);
                s2[i] = ffma2(q.u2[1], k.u2[1], s2[i]);
            }
        }
        float s[8];
#pragma unroll
        for (int i = 0; i < 8; i++) {
            float lo = __uint_as_float((uint32_t)s2[i]);
            float hi = __uint_as_float((uint32_t)(s2[i] >> 32));
            s[i] = lo + hi;
        }
        const int cg = kt * 32 + lane;
        const bool need_mask = (kt >= 2 * qi);
#pragma unroll
        for (int i = 0; i < 8; i++) {
            float v = s[i] * 0.125f;
            if (need_mask) {
                int rg = qi*64 + wid*8 + i;
                if (cg > rg) v = -1e30f;
            }
            s[i] = v;
        }
#pragma unroll
        for (int i = 0; i < 8; i++) {
            float tmax = s[i];
#pragma unroll
            for (int off = 16; off > 0; off >>= 1)
                tmax = fmaxf(tmax, __shfl_xor_sync(0xffffffffu, tmax, off));
            float mn = fmaxf(m[i], tmax);
            float p = __expf(s[i] - mn);
            float psum = p;
#pragma unroll
            for (int off = 16; off > 0; off >>= 1)
                psum += __shfl_xor_sync(0xffffffffu, psum, off);
            float alpha = __expf(m[i] - mn);
            lsum[i] = lsum[i] * alpha + psum;
            acc0[i] *= alpha; acc1[i] *= alpha;
            m[i] = mn;
            Ps[(wid*8 + i) * PADP + lane] = p;
        }
        __syncwarp();
#pragma unroll
        for (int c4 = 0; c4 < 8; c4++) {
            float v00 = Vs[(c4*4+0)*PADQ + lane];
            float v10 = Vs[(c4*4+1)*PADQ + lane];
            float v20 = Vs[(c4*4+2)*PADQ + lane];
            float v30 = Vs[(c4*4+3)*PADQ + lane];
            float v01 = Vs[(c4*4+0)*PADQ + lane + 32];
            float v11 = Vs[(c4*4+1)*PADQ + lane + 32];
            float v21 = Vs[(c4*4+2)*PADQ + lane + 32];
            float v31 = Vs[(c4*4+3)*PADQ + lane + 32];
#pragma unroll
            for (int i = 0; i < 8; i++) {
                float4 p = *(const float4*)&Ps[(wid*8 + i) * PADP + c4*4];
                acc0[i] += p.x*v00 + p.y*v10 + p.z*v20 + p.w*v30;
                acc1[i] += p.x*v01 + p.y*v11 + p.z*v21 + p.w*v31;
            }
        }
    }
#pragma unroll
    for (int i = 0; i < 8; i++) {
        float inv = 1.0f / lsum[i];
        int rg = qi*64 + wid*8 + i;
        size_t o = ((size_t)(b * LL + rg) * HH + h) * DHD;
        O[o + pidx(lane)]      = rnatf32(acc0[i] * inv);
        O[o + pidx(lane + 32)] = rnatf32(acc1[i] * inv);
    }
}

// ============================================================
// LayerNorm (ddof=1, (std+eps)); optional permuted+rounded 2nd output
// ============================================================
__global__ void __launch_bounds__(256) ln_kernel(
    const float* __restrict__ X, const float* __restrict__ gamma,
    const float* __restrict__ beta, float* __restrict__ Y,
    float* __restrict__ Yr)
{
    const int row = blockIdx.x;
    const int tid = threadIdx.x;
    const int lane = tid & 31, wid = tid >> 5;
    __shared__ float red[8];

    float4 v = *(const float4*)&X[(size_t)row * DD + tid * 4];

    float s = v.x + v.y + v.z + v.w;
#pragma unroll
    for (int off = 16; off > 0; off >>= 1) s += __shfl_xor_sync(0xffffffffu, s, off);
    if (lane == 0) red[wid] = s;
    __syncthreads();
    float mean = 0.f;
#pragma unroll
    for (int i = 0; i < 8; i++) mean += red[i];
    mean *= (1.0f / 1024.f);
    __syncthreads();

    float dx = v.x - mean, dy = v.y - mean, dz = v.z - mean, dw = v.w - mean;
    float ss = dx*dx + dy*dy + dz*dz + dw*dw;
#pragma unroll
    for (int off = 16; off > 0; off >>= 1) ss += __shfl_xor_sync(0xffffffffu, ss, off);
    if (lane == 0) red[wid] = ss;
    __syncthreads();
    float var = 0.f;
#pragma unroll
    for (int i = 0; i < 8; i++) var += red[i];
    var *= (1.0f / 1023.f);
    float istd = 1.0f / (sqrtf(var) + 1e-6f);

    float4 g  = *(const float4*)&gamma[tid * 4];
    float4 bb = *(const float4*)&beta[tid * 4];
    float o0 = dx * istd * g.x + bb.x;
    float o1 = dy * istd * g.y + bb.y;
    float o2 = dz * istd * g.z + bb.z;
    float o3 = dw * istd * g.w + bb.w;
    float4 out; out.x = o0; out.y = o1; out.z = o2; out.w = o3;
    *(float4*)&Y[(size_t)row * DD + tid * 4] = out;
    if (Yr) {
        // permuted positions: base 4*(tid&~1), stride-2 within the 8-group
        int base = 4 * (tid & ~1) + (tid & 1);
        float* yr = Yr + (size_t)row * DD + base;
        yr[0] = rnatf32(o0); yr[2] = rnatf32(o1);
        yr[4] = rnatf32(o2); yr[6] = rnatf32(o3);
    }
}

// ============================================================
extern "C" void kernel_launch(void* const* d_in, const int* in_sizes, int n_in,
                              void* d_out, int out_size)
{
    const float* x     = (const float*)d_in[0];
    const float* Wqkv  = (const float*)d_in[2];
    const float* bqkv  = (const float*)d_in[3];
    const float* Wo    = (const float*)d_in[4];
    const float* bo    = (const float*)d_in[5];
    const float* ln1_a = (const float*)d_in[6];
    const float* ln1_b = (const float*)d_in[7];
    const float* W1    = (const float*)d_in[8];
    const float* b1    = (const float*)d_in[9];
    const float* W2    = (const float*)d_in[10];
    const float* b2    = (const float*)d_in[11];
    const float* ln2_a = (const float*)d_in[12];
    const float* ln2_b = (const float*)d_in[13];
    float* out = (float*)d_out;

    float *qkv, *attn, *t0, *h1, *h1r, *ffn, *xr, *wqkvr, *wor, *w1r, *w2r;
    cudaGetSymbolAddress((void**)&qkv,   g_qkv);
    cudaGetSymbolAddress((void**)&attn,  g_attn);
    cudaGetSymbolAddress((void**)&t0,    g_t0);
    cudaGetSymbolAddress((void**)&h1,    g_h1);
    cudaGetSymbolAddress((void**)&h1r,   g_h1r);
    cudaGetSymbolAddress((void**)&ffn,   g_ffn);
    cudaGetSymbolAddress((void**)&xr,    g_xr);
    cudaGetSymbolAddress((void**)&wqkvr, g_wqkvr);
    cudaGetSymbolAddress((void**)&wor,   g_wor);
    cudaGetSymbolAddress((void**)&w1r,   g_w1r);
    cudaGetSymbolAddress((void**)&w2r,   g_w2r);

    const int SMEM256 = NSLOT * (128 + 256) * BK * 4;  // 196608
    const int SMEM128 = NSLOT * (128 + 128) * BK * 4;  // 131072
    cudaFuncSetAttribute(gemm_mma<256,false,false,false>, cudaFuncAttributeMaxDynamicSharedMemorySize, SMEM256);
    cudaFuncSetAttribute(gemm_mma<256,true ,false,true >, cudaFuncAttributeMaxDynamicSharedMemorySize, SMEM256);
    cudaFuncSetAttribute(gemm_mma<128,false,true ,false>, cudaFuncAttributeMaxDynamicSharedMemorySize, SMEM128);

    dim3 blk(256);

    // round+permute all GEMM A/B operands
    round_perm_kernel<<<(MTOT*DD/8 + 255)/256, blk>>>(x, xr, MTOT*DD/8);
    round_perm_kernel<<<(3*DD*DD/8 + 255)/256, blk>>>(Wqkv, wqkvr, 3*DD*DD/8);
    round_perm_kernel<<<(DD*DD/8 + 255)/256, blk>>>(Wo, wor, DD*DD/8);
    round_perm_kernel<<<(DFFN*DD/8 + 255)/256, blk>>>(W1, w1r, DFFN*DD/8);
    round_perm_kernel<<<(DD*DFFN/8 + 255)/256, blk>>>(W2, w2r, DD*DFFN/8);

    // 1) qkv = x @ Wqkv^T + bqkv                  [4096 x 3072] K=1024
    gemm_mma<256,false,false,false><<<dim3(3072/256, MTOT/128), blk, SMEM256>>>(
        xr, wqkvr, bqkv, nullptr, qkv, MTOT, 3*DD, DD);

    // 2) causal flash attention -> attn (permuted + tf32-rounded)
    attn_kernel<<<dim3(LL/64, HH, BBAT), blk>>>(qkv, attn);

    // 3) t0 = attn @ Wo^T + bo + x
    gemm_mma<128,false,true,false><<<dim3(DD/128, MTOT/128), blk, SMEM128>>>(
        attn, wor, bo, x, t0, MTOT, DD, DD);

    // 4) h1 = LN1(t0), h1r = permuted+rounded
    ln_kernel<<<MTOT, blk>>>(t0, ln1_a, ln1_b, h1, h1r);

    // 5) ffn = perm(round(relu(h1r @ W1^T + b1)))  [4096 x 4096] K=1024
    gemm_mma<256,true,false,true><<<dim3(DFFN/256, MTOT/128), blk, SMEM256>>>(
        h1r, w1r, b1, nullptr, ffn, MTOT, DFFN, DD);

    // 6) t0 = ffn @ W2^T + b2 + h1                 [4096 x 1024] K=4096
    gemm_mma<128,false,true,false><<<dim3(DD/128, MTOT/128), blk, SMEM128>>>(
        ffn, w2r, b2, h1, t0, MTOT, DD, DFFN);

    // 7) out = LN2(t0)
    ln_kernel<<<MTOT, blk>>>(t0, ln2_a, ln2_b, out, nullptr);
}

// round 8
// speedup vs baseline: 1.5880x; 1.5880x over previous
#include <cuda_runtime.h>
#include <cstdint>
#include <math.h>

#define BBAT 2
#define LL   2048
#define DD   1024
#define HH   16
#define DHD  64
#define DFFN 4096
#define MTOT (BBAT*LL)   // 4096

// ---- scratch (__device__ globals; no allocation allowed) ----
__device__ float g_qkv  [(size_t)MTOT*3*DD];
__device__ float g_attn [(size_t)MTOT*DD];
__device__ float g_t0   [(size_t)MTOT*DD];
__device__ float g_h1   [(size_t)MTOT*DD];
__device__ float g_h1r  [(size_t)MTOT*DD];
__device__ float g_ffn  [(size_t)MTOT*DFFN];
__device__ float g_xr   [(size_t)MTOT*DD];
__device__ float g_wqkvr[(size_t)3*DD*DD];
__device__ float g_wor  [(size_t)DD*DD];
__device__ float g_w1r  [(size_t)DFFN*DD];
__device__ float g_w2r  [(size_t)DD*DFFN];

// ============================================================
// Helpers
// ============================================================
__device__ __forceinline__ float rnatf32(float x) {
    uint32_t r; asm("cvt.rna.tf32.f32 %0, %1;" : "=r"(r) : "f"(x));
    return __uint_as_float(r);
}
__device__ __forceinline__ void mma8(float* c, uint32_t a0, uint32_t a1,
                                     uint32_t a2, uint32_t a3,
                                     uint32_t b0, uint32_t b1) {
    asm volatile(
        "mma.sync.aligned.m16n8k8.row.col.f32.tf32.tf32.f32 "
        "{%0,%1,%2,%3}, {%4,%5,%6,%7}, {%8,%9}, {%0,%1,%2,%3};\n"
        : "+f"(c[0]), "+f"(c[1]), "+f"(c[2]), "+f"(c[3])
        : "r"(a0), "r"(a1), "r"(a2), "r"(a3), "r"(b0), "r"(b1));
}
__device__ __forceinline__ void cp_async16(uint32_t dst, const void* src) {
    asm volatile("cp.async.cg.shared.global [%0], [%1], 16;\n" :: "r"(dst), "l"(src));
}
__device__ __forceinline__ void cp_commit() { asm volatile("cp.async.commit_group;\n"); }
template<int N> __device__ __forceinline__ void cp_wait() {
    asm volatile("cp.async.wait_group %0;\n" :: "n"(N));
}
__device__ __forceinline__ uint64_t ffma2(uint64_t a, uint64_t b, uint64_t c) {
    uint64_t d;
    asm("fma.rn.f32x2 %0, %1, %2, %3;" : "=l"(d) : "l"(a), "l"(b), "l"(c));
    return d;
}
// permuted position of element k within its 8-group (pairs (k,k+4) adjacent)
__device__ __forceinline__ int pidx(int d) {
    return (d & ~7) + 2 * (d & 3) + ((d >> 2) & 1);
}

// ============================================================
// round+permute: groups of 8 stored as [k0,k4,k1,k5,k2,k6,k3,k7], rna-tf32
// ============================================================
__global__ void __launch_bounds__(256) round_perm_kernel(
    const float* __restrict__ in, float* __restrict__ out, int n8)
{
    int i = blockIdx.x * 256 + threadIdx.x;
    if (i < n8) {
        float4 a = *(const float4*)&in[(size_t)i * 8];
        float4 b = *(const float4*)&in[(size_t)i * 8 + 4];
        float4 o1, o2;
        o1.x = rnatf32(a.x); o1.y = rnatf32(b.x); o1.z = rnatf32(a.y); o1.w = rnatf32(b.y);
        o2.x = rnatf32(a.z); o2.y = rnatf32(b.z); o2.z = rnatf32(a.w); o2.w = rnatf32(b.w);
        *(float4*)&out[(size_t)i * 8]     = o1;
        *(float4*)&out[(size_t)i * 8 + 4] = o2;
    }
}

// ============================================================
// TF32 mma.sync GEMM on pre-permuted operands.
// C[M,N] = A[M,K] @ W[N,K]^T + bias (+res)(relu)(perm+round out)
// Block 128x128, BK=32, 8 warps (2x4), warp tile 64x32, NI=4.
// Smem rows of 32 floats, k-groups XOR-swizzled by (row&3): LDS.64
// fragment loads conflict-free. 3-stage cp.async ring, 2 CTAs/SM.
// ============================================================
#define BK 32
#define NSLOT 3
#define STAGE_F ((128 + 128) * BK)          // 8192 floats = 32KB
#define GEMM_SMEM (NSLOT * STAGE_F * 4)     // 98304 B

template<bool RELU, bool RES, bool PERM>
__global__ void __launch_bounds__(256, 2) gemm_mma(
    const float* __restrict__ A, const float* __restrict__ W,
    const float* __restrict__ bias, const float* __restrict__ res,
    float* __restrict__ C, int M, int N, int K)
{
    extern __shared__ float smemf[];
    const uint32_t sbase = (uint32_t)__cvta_generic_to_shared(smemf);

    const int tid = threadIdx.x;
    const int lane = tid & 31, wid = tid >> 5;
    const int bm = blockIdx.y * 128, bn = blockIdx.x * 128;
    const int wm = (wid >> 2) * 64;
    const int wn = (wid & 3) * 32;
    const int gid = lane >> 2, tig = lane & 3;
    const int T = K / BK;

    float acc[4][4][4];
#pragma unroll
    for (int mi = 0; mi < 4; mi++)
#pragma unroll
        for (int ni = 0; ni < 4; ni++)
#pragma unroll
            for (int r = 0; r < 4; r++) acc[mi][ni][r] = 0.f;

    auto load_tile = [&](int t, int slot) {
        const uint32_t st = sbase + (uint32_t)slot * (STAGE_F * 4);
        const int kt = t * BK;
#pragma unroll
        for (int i = 0; i < 4; i++) {           // A: 1024 chunks of 16B
            int c = tid + i * 256;
            int r = c >> 3, h = c & 7;
            uint32_t dst = st + (uint32_t)(r * 128 + (((h >> 1) ^ (r & 3)) * 32) + (h & 1) * 16);
            cp_async16(dst, A + (size_t)(bm + r) * K + kt + h * 4);
        }
        const uint32_t stb = st + 128 * BK * 4;
#pragma unroll
        for (int i = 0; i < 4; i++) {           // B: 1024 chunks of 16B
            int c = tid + i * 256;
            int r = c >> 3, h = c & 7;
            uint32_t dst = stb + (uint32_t)(r * 128 + (((h >> 1) ^ (r & 3)) * 32) + (h & 1) * 16);
            cp_async16(dst, W + (size_t)(bn + r) * K + kt + h * 4);
        }
    };

    load_tile(0, 0); cp_commit();
    load_tile(1, 1); cp_commit();

    int sl = 0;        // compute slot for tile t
    int sl_ld = 2;     // load slot for tile t+2
    for (int t = 0; t < T; t++) {
        if (t + 2 < T) load_tile(t + 2, sl_ld);
        cp_commit();
        cp_wait<2>();
        __syncthreads();

        const float* Ab = smemf + (size_t)sl * STAGE_F;
        const float* Bb = Ab + 128 * BK;
#pragma unroll
        for (int ks = 0; ks < 4; ks++) {
            const int sw = (ks ^ (gid & 3)) * 8 + tig * 2;
            float2 fa[4][2];
#pragma unroll
            for (int mi = 0; mi < 4; mi++) {
                const float* p = Ab + (wm + mi * 16 + gid) * 32 + sw;
                fa[mi][0] = *(const float2*)p;
                fa[mi][1] = *(const float2*)(p + 8 * 32);
            }
            float2 fb[4];
#pragma unroll
            for (int ni = 0; ni < 4; ni++) {
                const float* p = Bb + (wn + ni * 8 + gid) * 32 + sw;
                fb[ni] = *(const float2*)p;
            }
#pragma unroll
            for (int mi = 0; mi < 4; mi++)
#pragma unroll
                for (int ni = 0; ni < 4; ni++)
                    mma8(acc[mi][ni],
                         __float_as_uint(fa[mi][0].x), __float_as_uint(fa[mi][1].x),
                         __float_as_uint(fa[mi][0].y), __float_as_uint(fa[mi][1].y),
                         __float_as_uint(fb[ni].x),    __float_as_uint(fb[ni].y));
        }
        __syncthreads();
        sl    = (sl    == 2) ? 0 : sl + 1;
        sl_ld = (sl_ld == 2) ? 0 : sl_ld + 1;
    }

    // epilogue
#pragma unroll
    for (int ni = 0; ni < 4; ni++) {
        const int cb = bn + wn + ni * 8;
        const int c0 = 2 * tig, c1 = 2 * tig + 1;
        const float b0 = bias[cb + c0], b1 = bias[cb + c1];
#pragma unroll
        for (int mi = 0; mi < 4; mi++) {
            const int row = bm + wm + mi * 16 + gid;
#pragma unroll
            for (int rr = 0; rr < 2; rr++) {
                const int r = row + rr * 8;
                float v0 = acc[mi][ni][rr * 2 + 0] + b0;
                float v1 = acc[mi][ni][rr * 2 + 1] + b1;
                size_t off = (size_t)r * N + cb + c0;
                if (RES) { v0 += res[off]; v1 += res[off + 1]; }
                if (RELU) { v0 = fmaxf(v0, 0.f); v1 = fmaxf(v1, 0.f); }
                if (PERM) {
                    C[(size_t)r * N + cb + pidx(c0)] = rnatf32(v0);
                    C[(size_t)r * N + cb + pidx(c1)] = rnatf32(v1);
                } else {
                    float2 o; o.x = v0; o.y = v1;
                    *(float2*)&C[off] = o;
                }
            }
        }
    }
}

// ============================================================
// Causal flash attention, fp32 + f32x2 QK. Output permuted+tf32-rounded.
// ============================================================
#define PADQ 68
#define PADP 36
union F4U2 { float4 f4; uint64_t u2[2]; };

__global__ void __launch_bounds__(256) attn_kernel(
    const float* __restrict__ qkv, float* __restrict__ O)
{
    __shared__ float Qs[64 * PADQ];
    __shared__ float Ks[32 * PADQ];
    __shared__ float Vs[32 * PADQ];
    __shared__ float Ps[64 * PADP];

    const int qi = blockIdx.x, h = blockIdx.y, b = blockIdx.z;
    const int tid = threadIdx.x, lane = tid & 31, wid = tid >> 5;
    const size_t qbase = (size_t)b * LL * 3 * DD + (size_t)h * DHD;

#pragma unroll
    for (int i = 0; i < 4; i++) {
        int f = i * 256 + tid;
        int r = f >> 4, d4 = f & 15;
        float4 v = *(const float4*)&qkv[qbase + (size_t)(qi*64 + r) * 3072 + d4*4];
        *(float4*)&Qs[r * PADQ + d4 * 4] = v;
    }

    float m[8], lsum[8], acc0[8], acc1[8];
#pragma unroll
    for (int i = 0; i < 8; i++) { m[i] = -1e30f; lsum[i] = 0.f; acc0[i] = 0.f; acc1[i] = 0.f; }

    const int ktmax = 2 * qi + 1;
    for (int kt = 0; kt <= ktmax; kt++) {
        __syncthreads();
#pragma unroll
        for (int i = 0; i < 2; i++) {
            int f = i * 256 + tid;
            int r = f >> 4, d4 = f & 15;
            size_t grow = qbase + (size_t)(kt*32 + r) * 3072 + d4*4;
            *(float4*)&Ks[r * PADQ + d4*4] = *(const float4*)&qkv[grow + 1024];
            *(float4*)&Vs[r * PADQ + d4*4] = *(const float4*)&qkv[grow + 2048];
        }
        __syncthreads();

        uint64_t s2[8];
#pragma unroll
        for (int i = 0; i < 8; i++) s2[i] = 0ull;
#pragma unroll
        for (int d4 = 0; d4 < 16; d4++) {
            F4U2 k; k.f4 = *(const float4*)&Ks[lane * PADQ + d4*4];
#pragma unroll
            for (int i = 0; i < 8; i++) {
                F4U2 q; q.f4 = *(const float4*)&Qs[(wid*8 + i) * PADQ + d4*4];
                s2[i] = ffma2(q.u2[0], k.u2[0], s2[i]);
                s2[i] = ffma2(q.u2[1], k.u2[1], s2[i]);
            }
        }
        float s[8];
#pragma unroll
        for (int i = 0; i < 8; i++) {
            float lo = __uint_as_float((uint32_t)s2[i]);
            float hi = __uint_as_float((uint32_t)(s2[i] >> 32));
            s[i] = lo + hi;
        }
        const int cg = kt * 32 + lane;
        const bool need_mask = (kt >= 2 * qi);
#pragma unroll
        for (int i = 0; i < 8; i++) {
            float v = s[i] * 0.125f;
            if (need_mask) {
                int rg = qi*64 + wid*8 + i;
                if (cg > rg) v = -1e30f;
            }
            s[i] = v;
        }
#pragma unroll
        for (int i = 0; i < 8; i++) {
            float tmax = s[i];
#pragma unroll
            for (int off = 16; off > 0; off >>= 1)
                tmax = fmaxf(tmax, __shfl_xor_sync(0xffffffffu, tmax, off));
            float mn = fmaxf(m[i], tmax);
            float p = __expf(s[i] - mn);
            float psum = p;
#pragma unroll
            for (int off = 16; off > 0; off >>= 1)
                psum += __shfl_xor_sync(0xffffffffu, psum, off);
            float alpha = __expf(m[i] - mn);
            lsum[i] = lsum[i] * alpha + psum;
            acc0[i] *= alpha; acc1[i] *= alpha;
            m[i] = mn;
            Ps[(wid*8 + i) * PADP + lane] = p;
        }
        __syncwarp();
#pragma unroll
        for (int c4 = 0; c4 < 8; c4++) {
            float v00 = Vs[(c4*4+0)*PADQ + lane];
            float v10 = Vs[(c4*4+1)*PADQ + lane];
            float v20 = Vs[(c4*4+2)*PADQ + lane];
            float v30 = Vs[(c4*4+3)*PADQ + lane];
            float v01 = Vs[(c4*4+0)*PADQ + lane + 32];
            float v11 = Vs[(c4*4+1)*PADQ + lane + 32];
            float v21 = Vs[(c4*4+2)*PADQ + lane + 32];
            float v31 = Vs[(c4*4+3)*PADQ + lane + 32];
#pragma unroll
            for (int i = 0; i < 8; i++) {
                float4 p = *(const float4*)&Ps[(wid*8 + i) * PADP + c4*4];
                acc0[i] += p.x*v00 + p.y*v10 + p.z*v20 + p.w*v30;
                acc1[i] += p.x*v01 + p.y*v11 + p.z*v21 + p.w*v31;
            }
        }
    }
#pragma unroll
    for (int i = 0; i < 8; i++) {
        float inv = 1.0f / lsum[i];
        int rg = qi*64 + wid*8 + i;
        size_t o = ((size_t)(b * LL + rg) * HH + h) * DHD;
        O[o + pidx(lane)]      = rnatf32(acc0[i] * inv);
        O[o + pidx(lane + 32)] = rnatf32(acc1[i] * inv);
    }
}

// ============================================================
// LayerNorm (ddof=1, (std+eps)); optional permuted+rounded 2nd output
// ============================================================
__global__ void __launch_bounds__(256) ln_kernel(
    const float* __restrict__ X, const float* __restrict__ gamma,
    const float* __restrict__ beta, float* __restrict__ Y,
    float* __restrict__ Yr)
{
    const int row = blockIdx.x;
    const int tid = threadIdx.x;
    const int lane = tid & 31, wid = tid >> 5;
    __shared__ float red[8];

    float4 v = *(const float4*)&X[(size_t)row * DD + tid * 4];

    float s = v.x + v.y + v.z + v.w;
#pragma unroll
    for (int off = 16; off > 0; off >>= 1) s += __shfl_xor_sync(0xffffffffu, s, off);
    if (lane == 0) red[wid] = s;
    __syncthreads();
    float mean = 0.f;
#pragma unroll
    for (int i = 0; i < 8; i++) mean += red[i];
    mean *= (1.0f / 1024.f);
    __syncthreads();

    float dx = v.x - mean, dy = v.y - mean, dz = v.z - mean, dw = v.w - mean;
    float ss = dx*dx + dy*dy + dz*dz + dw*dw;
#pragma unroll
    for (int off = 16; off > 0; off >>= 1) ss += __shfl_xor_sync(0xffffffffu, ss, off);
    if (lane == 0) red[wid] = ss;
    __syncthreads();
    float var = 0.f;
#pragma unroll
    for (int i = 0; i < 8; i++) var += red[i];
    var *= (1.0f / 1023.f);
    float istd = 1.0f / (sqrtf(var) + 1e-6f);

    float4 g  = *(const float4*)&gamma[tid * 4];
    float4 bb = *(const float4*)&beta[tid * 4];
    float o0 = dx * istd * g.x + bb.x;
    float o1 = dy * istd * g.y + bb.y;
    float o2 = dz * istd * g.z + bb.z;
    float o3 = dw * istd * g.w + bb.w;
    float4 out; out.x = o0; out.y = o1; out.z = o2; out.w = o3;
    *(float4*)&Y[(size_t)row * DD + tid * 4] = out;
    if (Yr) {
        int base = 4 * (tid & ~1) + (tid & 1);
        float* yr = Yr + (size_t)row * DD + base;
        yr[0] = rnatf32(o0); yr[2] = rnatf32(o1);
        yr[4] = rnatf32(o2); yr[6] = rnatf32(o3);
    }
}

// ============================================================
extern "C" void kernel_launch(void* const* d_in, const int* in_sizes, int n_in,
                              void* d_out, int out_size)
{
    const float* x     = (const float*)d_in[0];
    const float* Wqkv  = (const float*)d_in[2];
    const float* bqkv  = (const float*)d_in[3];
    const float* Wo    = (const float*)d_in[4];
    const float* bo    = (const float*)d_in[5];
    const float* ln1_a = (const float*)d_in[6];
    const float* ln1_b = (const float*)d_in[7];
    const float* W1    = (const float*)d_in[8];
    const float* b1    = (const float*)d_in[9];
    const float* W2    = (const float*)d_in[10];
    const float* b2    = (const float*)d_in[11];
    const float* ln2_a = (const float*)d_in[12];
    const float* ln2_b = (const float*)d_in[13];
    float* out = (float*)d_out;

    float *qkv, *attn, *t0, *h1, *h1r, *ffn, *xr, *wqkvr, *wor, *w1r, *w2r;
    cudaGetSymbolAddress((void**)&qkv,   g_qkv);
    cudaGetSymbolAddress((void**)&attn,  g_attn);
    cudaGetSymbolAddress((void**)&t0,    g_t0);
    cudaGetSymbolAddress((void**)&h1,    g_h1);
    cudaGetSymbolAddress((void**)&h1r,   g_h1r);
    cudaGetSymbolAddress((void**)&ffn,   g_ffn);
    cudaGetSymbolAddress((void**)&xr,    g_xr);
    cudaGetSymbolAddress((void**)&wqkvr, g_wqkvr);
    cudaGetSymbolAddress((void**)&wor,   g_wor);
    cudaGetSymbolAddress((void**)&w1r,   g_w1r);
    cudaGetSymbolAddress((void**)&w2r,   g_w2r);

    cudaFuncSetAttribute(gemm_mma<false,false,false>, cudaFuncAttributeMaxDynamicSharedMemorySize, GEMM_SMEM);
    cudaFuncSetAttribute(gemm_mma<true ,false,true >, cudaFuncAttributeMaxDynamicSharedMemorySize, GEMM_SMEM);
    cudaFuncSetAttribute(gemm_mma<false,true ,false>, cudaFuncAttributeMaxDynamicSharedMemorySize, GEMM_SMEM);

    dim3 blk(256);

    // round+permute all GEMM A/B operands
    round_perm_kernel<<<(MTOT*DD/8 + 255)/256, blk>>>(x, xr, MTOT*DD/8);
    round_perm_kernel<<<(3*DD*DD/8 + 255)/256, blk>>>(Wqkv, wqkvr, 3*DD*DD/8);
    round_perm_kernel<<<(DD*DD/8 + 255)/256, blk>>>(Wo, wor, DD*DD/8);
    round_perm_kernel<<<(DFFN*DD/8 + 255)/256, blk>>>(W1, w1r, DFFN*DD/8);
    round_perm_kernel<<<(DD*DFFN/8 + 255)/256, blk>>>(W2, w2r, DD*DFFN/8);

    // 1) qkv = x @ Wqkv^T + bqkv                  [4096 x 3072] K=1024
    gemm_mma<false,false,false><<<dim3(3072/128, MTOT/128), blk, GEMM_SMEM>>>(
        xr, wqkvr, bqkv, nullptr, qkv, MTOT, 3*DD, DD);

    // 2) causal flash attention -> attn (permuted + tf32-rounded)
    attn_kernel<<<dim3(LL/64, HH, BBAT), blk>>>(qkv, attn);

    // 3) t0 = attn @ Wo^T + bo + x
    gemm_mma<false,true,false><<<dim3(DD/128, MTOT/128), blk, GEMM_SMEM>>>(
        attn, wor, bo, x, t0, MTOT, DD, DD);

    // 4) h1 = LN1(t0), h1r = permuted+rounded
    ln_kernel<<<MTOT, blk>>>(t0, ln1_a, ln1_b, h1, h1r);

    // 5) ffn = perm(round(relu(h1r @ W1^T + b1)))  [4096 x 4096] K=1024
    gemm_mma<true,false,true><<<dim3(DFFN/128, MTOT/128), blk, GEMM_SMEM>>>(
        h1r, w1r, b1, nullptr, ffn, MTOT, DFFN, DD);

    // 6) t0 = ffn @ W2^T + b2 + h1                 [4096 x 1024] K=4096
    gemm_mma<false,true,false><<<dim3(DD/128, MTOT/128), blk, GEMM_SMEM>>>(
        ffn, w2r, b2, h1, t0, MTOT, DD, DFFN);

    // 7) out = LN2(t0)
    ln_kernel<<<MTOT, blk>>>(t0, ln2_a, ln2_b, out, nullptr);
}

// round 9
// speedup vs baseline: 2.3072x; 1.4529x over previous
#include <cuda_runtime.h>
#include <cstdint>
#include <math.h>

#define BBAT 2
#define LL   2048
#define DD   1024
#define HH   16
#define DHD  64
#define DFFN 4096
#define MTOT (BBAT*LL)   // 4096

// ---- scratch (__device__ globals; no allocation allowed) ----
__device__ float g_qkv  [(size_t)MTOT*3*DD];
__device__ float g_attn [(size_t)MTOT*DD];
__device__ float g_t0   [(size_t)MTOT*DD];
__device__ float g_h1   [(size_t)MTOT*DD];
__device__ float g_h1r  [(size_t)MTOT*DD];
__device__ float g_ffn  [(size_t)MTOT*DFFN];
__device__ float g_xr   [(size_t)MTOT*DD];
__device__ float g_wqkvr[(size_t)3*DD*DD];
__device__ float g_wor  [(size_t)DD*DD];
__device__ float g_w1r  [(size_t)DFFN*DD];
__device__ float g_w2r  [(size_t)DD*DFFN];

// ============================================================
// Helpers
// ============================================================
__device__ __forceinline__ float rnatf32(float x) {
    uint32_t r; asm("cvt.rna.tf32.f32 %0, %1;" : "=r"(r) : "f"(x));
    return __uint_as_float(r);
}
__device__ __forceinline__ void mma8(float* c, uint32_t a0, uint32_t a1,
                                     uint32_t a2, uint32_t a3,
                                     uint32_t b0, uint32_t b1) {
    asm volatile(
        "mma.sync.aligned.m16n8k8.row.col.f32.tf32.tf32.f32 "
        "{%0,%1,%2,%3}, {%4,%5,%6,%7}, {%8,%9}, {%0,%1,%2,%3};\n"
        : "+f"(c[0]), "+f"(c[1]), "+f"(c[2]), "+f"(c[3])
        : "r"(a0), "r"(a1), "r"(a2), "r"(a3), "r"(b0), "r"(b1));
}
__device__ __forceinline__ void cp_async16(uint32_t dst, const void* src) {
    asm volatile("cp.async.cg.shared.global [%0], [%1], 16;\n" :: "r"(dst), "l"(src));
}
__device__ __forceinline__ void cp_commit() { asm volatile("cp.async.commit_group;\n"); }
template<int N> __device__ __forceinline__ void cp_wait() {
    asm volatile("cp.async.wait_group %0;\n" :: "n"(N));
}
// permuted position of element k within its 8-group (pairs (k,k+4) adjacent)
__device__ __forceinline__ int pidx(int d) {
    return (d & ~7) + 2 * (d & 3) + ((d >> 2) & 1);
}
__device__ __forceinline__ int pidx8(int c) {   // within-group version, c in 0..7
    return 2 * (c & 3) + ((c >> 2) & 1);
}

// ============================================================
// round+permute: groups of 8 stored as [k0,k4,k1,k5,k2,k6,k3,k7], rna-tf32
// ============================================================
__global__ void __launch_bounds__(256) round_perm_kernel(
    const float* __restrict__ in, float* __restrict__ out, int n8)
{
    int i = blockIdx.x * 256 + threadIdx.x;
    if (i < n8) {
        float4 a = *(const float4*)&in[(size_t)i * 8];
        float4 b = *(const float4*)&in[(size_t)i * 8 + 4];
        float4 o1, o2;
        o1.x = rnatf32(a.x); o1.y = rnatf32(b.x); o1.z = rnatf32(a.y); o1.w = rnatf32(b.y);
        o2.x = rnatf32(a.z); o2.y = rnatf32(b.z); o2.z = rnatf32(a.w); o2.w = rnatf32(b.w);
        *(float4*)&out[(size_t)i * 8]     = o1;
        *(float4*)&out[(size_t)i * 8 + 4] = o2;
    }
}

// ============================================================
// TF32 mma.sync GEMM on pre-permuted operands. (unchanged from R8)
// ============================================================
#define BK 32
#define NSLOT 3
#define STAGE_F ((128 + 128) * BK)          // 8192 floats = 32KB
#define GEMM_SMEM (NSLOT * STAGE_F * 4)     // 98304 B

template<bool RELU, bool RES, bool PERM>
__global__ void __launch_bounds__(256, 2) gemm_mma(
    const float* __restrict__ A, const float* __restrict__ W,
    const float* __restrict__ bias, const float* __restrict__ res,
    float* __restrict__ C, int M, int N, int K)
{
    extern __shared__ float smemf[];
    const uint32_t sbase = (uint32_t)__cvta_generic_to_shared(smemf);

    const int tid = threadIdx.x;
    const int lane = tid & 31, wid = tid >> 5;
    const int bm = blockIdx.y * 128, bn = blockIdx.x * 128;
    const int wm = (wid >> 2) * 64;
    const int wn = (wid & 3) * 32;
    const int gid = lane >> 2, tig = lane & 3;
    const int T = K / BK;

    float acc[4][4][4];
#pragma unroll
    for (int mi = 0; mi < 4; mi++)
#pragma unroll
        for (int ni = 0; ni < 4; ni++)
#pragma unroll
            for (int r = 0; r < 4; r++) acc[mi][ni][r] = 0.f;

    auto load_tile = [&](int t, int slot) {
        const uint32_t st = sbase + (uint32_t)slot * (STAGE_F * 4);
        const int kt = t * BK;
#pragma unroll
        for (int i = 0; i < 4; i++) {
            int c = tid + i * 256;
            int r = c >> 3, h = c & 7;
            uint32_t dst = st + (uint32_t)(r * 128 + (((h >> 1) ^ (r & 3)) * 32) + (h & 1) * 16);
            cp_async16(dst, A + (size_t)(bm + r) * K + kt + h * 4);
        }
        const uint32_t stb = st + 128 * BK * 4;
#pragma unroll
        for (int i = 0; i < 4; i++) {
            int c = tid + i * 256;
            int r = c >> 3, h = c & 7;
            uint32_t dst = stb + (uint32_t)(r * 128 + (((h >> 1) ^ (r & 3)) * 32) + (h & 1) * 16);
            cp_async16(dst, W + (size_t)(bn + r) * K + kt + h * 4);
        }
    };

    load_tile(0, 0); cp_commit();
    load_tile(1, 1); cp_commit();

    int sl = 0, sl_ld = 2;
    for (int t = 0; t < T; t++) {
        if (t + 2 < T) load_tile(t + 2, sl_ld);
        cp_commit();
        cp_wait<2>();
        __syncthreads();

        const float* Ab = smemf + (size_t)sl * STAGE_F;
        const float* Bb = Ab + 128 * BK;
#pragma unroll
        for (int ks = 0; ks < 4; ks++) {
            const int sw = (ks ^ (gid & 3)) * 8 + tig * 2;
            float2 fa[4][2];
#pragma unroll
            for (int mi = 0; mi < 4; mi++) {
                const float* p = Ab + (wm + mi * 16 + gid) * 32 + sw;
                fa[mi][0] = *(const float2*)p;
                fa[mi][1] = *(const float2*)(p + 8 * 32);
            }
            float2 fb[4];
#pragma unroll
            for (int ni = 0; ni < 4; ni++) {
                const float* p = Bb + (wn + ni * 8 + gid) * 32 + sw;
                fb[ni] = *(const float2*)p;
            }
#pragma unroll
            for (int mi = 0; mi < 4; mi++)
#pragma unroll
                for (int ni = 0; ni < 4; ni++)
                    mma8(acc[mi][ni],
                         __float_as_uint(fa[mi][0].x), __float_as_uint(fa[mi][1].x),
                         __float_as_uint(fa[mi][0].y), __float_as_uint(fa[mi][1].y),
                         __float_as_uint(fb[ni].x),    __float_as_uint(fb[ni].y));
        }
        __syncthreads();
        sl    = (sl    == 2) ? 0 : sl + 1;
        sl_ld = (sl_ld == 2) ? 0 : sl_ld + 1;
    }

#pragma unroll
    for (int ni = 0; ni < 4; ni++) {
        const int cb = bn + wn + ni * 8;
        const int c0 = 2 * tig, c1 = 2 * tig + 1;
        const float b0 = bias[cb + c0], b1 = bias[cb + c1];
#pragma unroll
        for (int mi = 0; mi < 4; mi++) {
            const int row = bm + wm + mi * 16 + gid;
#pragma unroll
            for (int rr = 0; rr < 2; rr++) {
                const int r = row + rr * 8;
                float v0 = acc[mi][ni][rr * 2 + 0] + b0;
                float v1 = acc[mi][ni][rr * 2 + 1] + b1;
                size_t off = (size_t)r * N + cb + c0;
                if (RES) { v0 += res[off]; v1 += res[off + 1]; }
                if (RELU) { v0 = fmaxf(v0, 0.f); v1 = fmaxf(v1, 0.f); }
                if (PERM) {
                    C[(size_t)r * N + cb + pidx(c0)] = rnatf32(v0);
                    C[(size_t)r * N + cb + pidx(c1)] = rnatf32(v1);
                } else {
                    float2 o; o.x = v0; o.y = v1;
                    *(float2*)&C[off] = o;
                }
            }
        }
    }
}

// ============================================================
// Tensor-core causal flash attention (tf32 mma).
// BQ=128 q-rows/block, BK=32 keys/tile, DH=64. 8 warps, warp = 16 rows.
// Smem operands pre-permuted ((k,k+4) adjacent) + XOR-(row&3) group swizzle.
// Output written permuted+rounded for the Wo GEMM.
// ============================================================
#define AQ 128
#define ATTN_SMEM ((128*64 + 32*64 + 64*32 + 128*32) * 4)   // 65536 B

__global__ void __launch_bounds__(256) attn_tc(
    const float* __restrict__ qkv, float* __restrict__ O)
{
    extern __shared__ float sm[];
    float* Qs = sm;                    // [128][64]
    float* Ks = sm + 128 * 64;         // [32][64]
    float* Vt = Ks + 32 * 64;          // [64][32]  (transposed V)
    float* Ps = Vt + 64 * 32;          // [128][32]

    const int qi = blockIdx.x, h = blockIdx.y, b = blockIdx.z;
    const int tid = threadIdx.x, lane = tid & 31, wid = tid >> 5;
    const int gid = lane >> 2, tig = lane & 3;
    const size_t qbase = (size_t)b * LL * 3 * DD + (size_t)h * DHD;

    // ---- load Q tile 128x64, rounded + permuted + group-XOR ----
#pragma unroll
    for (int i = 0; i < 8; i++) {
        int f = i * 256 + tid;
        int r = f >> 4, d4 = (f & 15) * 4;
        float4 v = *(const float4*)&qkv[qbase + (size_t)(qi * AQ + r) * 3072 + d4];
        float e[4] = {v.x, v.y, v.z, v.w};
        int g = d4 >> 3;
        float* qrow = Qs + r * 64 + ((g ^ (r & 3)) * 8);
#pragma unroll
        for (int ee = 0; ee < 4; ee++) {
            int d = d4 + ee;
            qrow[pidx8(d & 7)] = rnatf32(e[ee]);
        }
    }

    float m0 = -1e30f, m1 = -1e30f, l0 = 0.f, l1 = 0.f;
    float oacc[8][4];
#pragma unroll
    for (int ni = 0; ni < 8; ni++)
#pragma unroll
        for (int c = 0; c < 4; c++) oacc[ni][c] = 0.f;

    const int r0 = 16 * wid + gid;             // local row (first half)
    const int rowg0 = qi * AQ + r0;            // global q row
    const int rowg1 = rowg0 + 8;
    const int xr = gid & 3;                    // XOR key for this warp's rows

    const int ktmax = 4 * qi + 3;
    for (int kt = 0; kt <= ktmax; kt++) {
        __syncthreads();
        // ---- load K tile 32x64 (perm+XOR), V tile transposed to Vt[64][32] ----
#pragma unroll
        for (int i = 0; i < 2; i++) {
            int f = i * 256 + tid;
            int r = f >> 4, d4 = (f & 15) * 4;
            size_t grow = qbase + (size_t)(kt * 32 + r) * 3072 + d4;
            float4 kv = *(const float4*)&qkv[grow + 1024];
            float4 vv = *(const float4*)&qkv[grow + 2048];
            float ke[4] = {kv.x, kv.y, kv.z, kv.w};
            float ve[4] = {vv.x, vv.y, vv.z, vv.w};
            int g = d4 >> 3;
            float* krow = Ks + r * 64 + ((g ^ (r & 3)) * 8);
            int sg = r >> 3, sp = pidx8(r & 7);
#pragma unroll
            for (int ee = 0; ee < 4; ee++) {
                int d = d4 + ee;
                krow[pidx8(d & 7)] = rnatf32(ke[ee]);
                Vt[d * 32 + ((sg ^ (d & 3)) * 8) + sp] = rnatf32(ve[ee]);
            }
        }
        __syncthreads();

        // ---- S = Q K^T : 16x32 per warp ----
        float sfr[4][4];
#pragma unroll
        for (int ni = 0; ni < 4; ni++)
#pragma unroll
            for (int c = 0; c < 4; c++) sfr[ni][c] = 0.f;
#pragma unroll
        for (int ks = 0; ks < 8; ks++) {
            const int sw = (ks ^ xr) * 8 + tig * 2;
            const float* pa = Qs + r0 * 64 + sw;
            float2 a02 = *(const float2*)pa;
            float2 a13 = *(const float2*)(pa + 8 * 64);
#pragma unroll
            for (int ni = 0; ni < 4; ni++) {
                float2 bb = *(const float2*)(Ks + (8 * ni + gid) * 64 + sw);
                mma8(sfr[ni],
                     __float_as_uint(a02.x), __float_as_uint(a13.x),
                     __float_as_uint(a02.y), __float_as_uint(a13.y),
                     __float_as_uint(bb.x), __float_as_uint(bb.y));
            }
        }

        // ---- scale, mask, online softmax (rows gid / gid+8) ----
        const bool domask = (kt >= 4 * qi);
        const int colbase = kt * 32;
        float p[4][4];
#pragma unroll
        for (int ni = 0; ni < 4; ni++)
#pragma unroll
            for (int c = 0; c < 4; c++) {
                float v = sfr[ni][c] * 0.125f;
                if (domask) {
                    int col = colbase + 8 * ni + 2 * tig + (c & 1);
                    int rg = (c < 2) ? rowg0 : rowg1;
                    if (col > rg) v = -1e30f;
                }
                p[ni][c] = v;
            }
        // row-half 0 (c0,c1), row-half 1 (c2,c3)
#pragma unroll
        for (int half = 0; half < 2; half++) {
            float rmax = -1e30f;
#pragma unroll
            for (int ni = 0; ni < 4; ni++) {
                rmax = fmaxf(rmax, p[ni][half * 2]);
                rmax = fmaxf(rmax, p[ni][half * 2 + 1]);
            }
            rmax = fmaxf(rmax, __shfl_xor_sync(0xffffffffu, rmax, 1));
            rmax = fmaxf(rmax, __shfl_xor_sync(0xffffffffu, rmax, 2));
            float mprev = half ? m1 : m0;
            float mn = fmaxf(mprev, rmax);
            float alpha = __expf(mprev - mn);
            float psum = 0.f;
#pragma unroll
            for (int ni = 0; ni < 4; ni++) {
#pragma unroll
                for (int j = 0; j < 2; j++) {
                    float e = __expf(p[ni][half * 2 + j] - mn);
                    p[ni][half * 2 + j] = e;
                    psum += e;
                }
            }
            psum += __shfl_xor_sync(0xffffffffu, psum, 1);
            psum += __shfl_xor_sync(0xffffffffu, psum, 2);
            if (half == 0) { l0 = l0 * alpha + psum; m0 = mn; }
            else           { l1 = l1 * alpha + psum; m1 = mn; }
#pragma unroll
            for (int ni = 0; ni < 8; ni++) {
                oacc[ni][half * 2]     *= alpha;
                oacc[ni][half * 2 + 1] *= alpha;
            }
        }
        // ---- write P (rounded) to Ps, permuted + XOR ----
#pragma unroll
        for (int ni = 0; ni < 4; ni++) {
            float* prow0 = Ps + r0 * 32 + ((ni ^ xr) * 8);
            float* prow1 = prow0 + 8 * 32;
#pragma unroll
            for (int j = 0; j < 2; j++) {
                int pos = pidx8(2 * tig + j);
                prow0[pos] = rnatf32(p[ni][j]);
                prow1[pos] = rnatf32(p[ni][2 + j]);
            }
        }
        __syncwarp();

        // ---- O += P V ----
#pragma unroll
        for (int ksp = 0; ksp < 4; ksp++) {
            const int swp = (ksp ^ xr) * 8 + tig * 2;
            const float* pa = Ps + r0 * 32 + swp;
            float2 a02 = *(const float2*)pa;
            float2 a13 = *(const float2*)(pa + 8 * 32);
#pragma unroll
            for (int ni = 0; ni < 8; ni++) {
                const int d = 8 * ni + gid;
                float2 bb = *(const float2*)(Vt + d * 32 + ((ksp ^ (d & 3)) * 8) + tig * 2);
                mma8(oacc[ni],
                     __float_as_uint(a02.x), __float_as_uint(a13.x),
                     __float_as_uint(a02.y), __float_as_uint(a13.y),
                     __float_as_uint(bb.x), __float_as_uint(bb.y));
            }
        }
    }

    // ---- write O: [b, qrow, h, dh], permuted + rounded ----
    float inv0 = 1.0f / l0, inv1 = 1.0f / l1;
    size_t ob0 = ((size_t)(b * LL + rowg0) * HH + h) * DHD;
    size_t ob1 = ((size_t)(b * LL + rowg1) * HH + h) * DHD;
#pragma unroll
    for (int ni = 0; ni < 8; ni++) {
#pragma unroll
        for (int j = 0; j < 2; j++) {
            int pdh = 8 * ni + pidx8(2 * tig + j);
            O[ob0 + pdh] = rnatf32(oacc[ni][j] * inv0);
            O[ob1 + pdh] = rnatf32(oacc[ni][2 + j] * inv1);
        }
    }
}

// ============================================================
// LayerNorm (ddof=1, (std+eps)); optional permuted+rounded 2nd output
// ============================================================
__global__ void __launch_bounds__(256) ln_kernel(
    const float* __restrict__ X, const float* __restrict__ gamma,
    const float* __restrict__ beta, float* __restrict__ Y,
    float* __restrict__ Yr)
{
    const int row = blockIdx.x;
    const int tid = threadIdx.x;
    const int lane = tid & 31, wid = tid >> 5;
    __shared__ float red[8];

    float4 v = *(const float4*)&X[(size_t)row * DD + tid * 4];

    float s = v.x + v.y + v.z + v.w;
#pragma unroll
    for (int off = 16; off > 0; off >>= 1) s += __shfl_xor_sync(0xffffffffu, s, off);
    if (lane == 0) red[wid] = s;
    __syncthreads();
    float mean = 0.f;
#pragma unroll
    for (int i = 0; i < 8; i++) mean += red[i];
    mean *= (1.0f / 1024.f);
    __syncthreads();

    float dx = v.x - mean, dy = v.y - mean, dz = v.z - mean, dw = v.w - mean;
    float ss = dx*dx + dy*dy + dz*dz + dw*dw;
#pragma unroll
    for (int off = 16; off > 0; off >>= 1) ss += __shfl_xor_sync(0xffffffffu, ss, off);
    if (lane == 0) red[wid] = ss;
    __syncthreads();
    float var = 0.f;
#pragma unroll
    for (int i = 0; i < 8; i++) var += red[i];
    var *= (1.0f / 1023.f);
    float istd = 1.0f / (sqrtf(var) + 1e-6f);

    float4 g  = *(const float4*)&gamma[tid * 4];
    float4 bb = *(const float4*)&beta[tid * 4];
    float o0 = dx * istd * g.x + bb.x;
    float o1 = dy * istd * g.y + bb.y;
    float o2 = dz * istd * g.z + bb.z;
    float o3 = dw * istd * g.w + bb.w;
    float4 out; out.x = o0; out.y = o1; out.z = o2; out.w = o3;
    *(float4*)&Y[(size_t)row * DD + tid * 4] = out;
    if (Yr) {
        int base = 4 * (tid & ~1) + (tid & 1);
        float* yr = Yr + (size_t)row * DD + base;
        yr[0] = rnatf32(o0); yr[2] = rnatf32(o1);
        yr[4] = rnatf32(o2); yr[6] = rnatf32(o3);
    }
}

// ============================================================
extern "C" void kernel_launch(void* const* d_in, const int* in_sizes, int n_in,
                              void* d_out, int out_size)
{
    const float* x     = (const float*)d_in[0];
    const float* Wqkv  = (const float*)d_in[2];
    const float* bqkv  = (const float*)d_in[3];
    const float* Wo    = (const float*)d_in[4];
    const float* bo    = (const float*)d_in[5];
    const float* ln1_a = (const float*)d_in[6];
    const float* ln1_b = (const float*)d_in[7];
    const float* W1    = (const float*)d_in[8];
    const float* b1    = (const float*)d_in[9];
    const float* W2    = (const float*)d_in[10];
    const float* b2    = (const float*)d_in[11];
    const float* ln2_a = (const float*)d_in[12];
    const float* ln2_b = (const float*)d_in[13];
    float* out = (float*)d_out;

    float *qkv, *attn, *t0, *h1, *h1r, *ffn, *xr, *wqkvr, *wor, *w1r, *w2r;
    cudaGetSymbolAddress((void**)&qkv,   g_qkv);
    cudaGetSymbolAddress((void**)&attn,  g_attn);
    cudaGetSymbolAddress((void**)&t0,    g_t0);
    cudaGetSymbolAddress((void**)&h1,    g_h1);
    cudaGetSymbolAddress((void**)&h1r,   g_h1r);
    cudaGetSymbolAddress((void**)&ffn,   g_ffn);
    cudaGetSymbolAddress((void**)&xr,    g_xr);
    cudaGetSymbolAddress((void**)&wqkvr, g_wqkvr);
    cudaGetSymbolAddress((void**)&wor,   g_wor);
    cudaGetSymbolAddress((void**)&w1r,   g_w1r);
    cudaGetSymbolAddress((void**)&w2r,   g_w2r);

    cudaFuncSetAttribute(gemm_mma<false,false,false>, cudaFuncAttributeMaxDynamicSharedMemorySize, GEMM_SMEM);
    cudaFuncSetAttribute(gemm_mma<true ,false,true >, cudaFuncAttributeMaxDynamicSharedMemorySize, GEMM_SMEM);
    cudaFuncSetAttribute(gemm_mma<false,true ,false>, cudaFuncAttributeMaxDynamicSharedMemorySize, GEMM_SMEM);
    cudaFuncSetAttribute(attn_tc, cudaFuncAttributeMaxDynamicSharedMemorySize, ATTN_SMEM);

    dim3 blk(256);

    // round+permute all GEMM A/B operands
    round_perm_kernel<<<(MTOT*DD/8 + 255)/256, blk>>>(x, xr, MTOT*DD/8);
    round_perm_kernel<<<(3*DD*DD/8 + 255)/256, blk>>>(Wqkv, wqkvr, 3*DD*DD/8);
    round_perm_kernel<<<(DD*DD/8 + 255)/256, blk>>>(Wo, wor, DD*DD/8);
    round_perm_kernel<<<(DFFN*DD/8 + 255)/256, blk>>>(W1, w1r, DFFN*DD/8);
    round_perm_kernel<<<(DD*DFFN/8 + 255)/256, blk>>>(W2, w2r, DD*DFFN/8);

    // 1) qkv = x @ Wqkv^T + bqkv                  [4096 x 3072] K=1024
    gemm_mma<false,false,false><<<dim3(3072/128, MTOT/128), blk, GEMM_SMEM>>>(
        xr, wqkvr, bqkv, nullptr, qkv, MTOT, 3*DD, DD);

    // 2) tensor-core causal flash attention -> attn (permuted + rounded)
    attn_tc<<<dim3(LL/AQ, HH, BBAT), blk, ATTN_SMEM>>>(qkv, attn);

    // 3) t0 = attn @ Wo^T + bo + x
    gemm_mma<false,true,false><<<dim3(DD/128, MTOT/128), blk, GEMM_SMEM>>>(
        attn, wor, bo, x, t0, MTOT, DD, DD);

    // 4) h1 = LN1(t0), h1r = permuted+rounded
    ln_kernel<<<MTOT, blk>>>(t0, ln1_a, ln1_b, h1, h1r);

    // 5) ffn = perm(round(relu(h1r @ W1^T + b1)))  [4096 x 4096] K=1024
    gemm_mma<true,false,true><<<dim3(DFFN/128, MTOT/128), blk, GEMM_SMEM>>>(
        h1r, w1r, b1, nullptr, ffn, MTOT, DFFN, DD);

    // 6) t0 = ffn @ W2^T + b2 + h1                 [4096 x 1024] K=4096
    gemm_mma<false,true,false><<<dim3(DD/128, MTOT/128), blk, GEMM_SMEM>>>(
        ffn, w2r, b2, h1, t0, MTOT, DD, DFFN);

    // 7) out = LN2(t0)
    ln_kernel<<<MTOT, blk>>>(t0, ln2_a, ln2_b, out, nullptr);
}

// round 10
// speedup vs baseline: 3.0847x; 1.3370x over previous
#include <cuda_runtime.h>
#include <cuda_fp16.h>
#include <cstdint>
#include <math.h>

#define BBAT 2
#define LL   2048
#define DD   1024
#define HH   16
#define DHD  64
#define DFFN 4096
#define MTOT (BBAT*LL)   // 4096

// ---- scratch (__device__ globals; no allocation allowed) ----
__device__ float  g_qkv  [(size_t)MTOT*3*DD];
__device__ __half g_attn [(size_t)MTOT*DD];
__device__ float  g_t0   [(size_t)MTOT*DD];
__device__ float  g_h1   [(size_t)MTOT*DD];
__device__ __half g_h1r  [(size_t)MTOT*DD];
__device__ __half g_ffn  [(size_t)MTOT*DFFN];
__device__ __half g_xr   [(size_t)MTOT*DD];
__device__ __half g_wqkvr[(size_t)3*DD*DD];
__device__ __half g_wor  [(size_t)DD*DD];
__device__ __half g_w1r  [(size_t)DFFN*DD];
__device__ __half g_w2r  [(size_t)DD*DFFN];

// ============================================================
// Helpers
// ============================================================
__device__ __forceinline__ float rnatf32(float x) {
    uint32_t r; asm("cvt.rna.tf32.f32 %0, %1;" : "=r"(r) : "f"(x));
    return __uint_as_float(r);
}
// tf32 mma (used by attention)
__device__ __forceinline__ void mma8(float* c, uint32_t a0, uint32_t a1,
                                     uint32_t a2, uint32_t a3,
                                     uint32_t b0, uint32_t b1) {
    asm volatile(
        "mma.sync.aligned.m16n8k8.row.col.f32.tf32.tf32.f32 "
        "{%0,%1,%2,%3}, {%4,%5,%6,%7}, {%8,%9}, {%0,%1,%2,%3};\n"
        : "+f"(c[0]), "+f"(c[1]), "+f"(c[2]), "+f"(c[3])
        : "r"(a0), "r"(a1), "r"(a2), "r"(a3), "r"(b0), "r"(b1));
}
// fp16 mma m16n8k16, fp32 accum
__device__ __forceinline__ void mma16h(float* c, uint32_t a0, uint32_t a1,
                                       uint32_t a2, uint32_t a3,
                                       uint32_t b0, uint32_t b1) {
    asm volatile(
        "mma.sync.aligned.m16n8k16.row.col.f32.f16.f16.f32 "
        "{%0,%1,%2,%3}, {%4,%5,%6,%7}, {%8,%9}, {%0,%1,%2,%3};\n"
        : "+f"(c[0]), "+f"(c[1]), "+f"(c[2]), "+f"(c[3])
        : "r"(a0), "r"(a1), "r"(a2), "r"(a3), "r"(b0), "r"(b1));
}
__device__ __forceinline__ void cp_async16(uint32_t dst, const void* src) {
    asm volatile("cp.async.cg.shared.global [%0], [%1], 16;\n" :: "r"(dst), "l"(src));
}
__device__ __forceinline__ void cp_commit() { asm volatile("cp.async.commit_group;\n"); }
template<int N> __device__ __forceinline__ void cp_wait() {
    asm volatile("cp.async.wait_group %0;\n" :: "n"(N));
}
// tf32 8-group permuted index (attention internals)
__device__ __forceinline__ int pidx8(int c) {
    return 2 * (c & 3) + ((c >> 2) & 1);
}
// fp16 16-group permuted index: order [0,1,8,9,2,3,10,11,4,5,12,13,6,7,14,15]
__device__ __forceinline__ int p16(int c) {
    return ((c & 7) >> 1) * 4 + ((c >> 3) & 1) * 2 + (c & 1);
}
__device__ __forceinline__ uint32_t h2u(__half2 h) {
    return *reinterpret_cast<uint32_t*>(&h);
}

// ============================================================
// fp32 -> fp16 convert + permute into 16-groups
// ============================================================
__global__ void __launch_bounds__(256) round_perm16(
    const float* __restrict__ in, __half* __restrict__ out, int n16)
{
    int i = blockIdx.x * 256 + threadIdx.x;
    if (i < n16) {
        const float4* src = (const float4*)(in + (size_t)i * 16);
        float4 v0 = src[0], v1 = src[1], v2 = src[2], v3 = src[3];
        uint4 o0, o1;
        o0.x = h2u(__floats2half2_rn(v0.x, v0.y));   // 0,1
        o0.y = h2u(__floats2half2_rn(v2.x, v2.y));   // 8,9
        o0.z = h2u(__floats2half2_rn(v0.z, v0.w));   // 2,3
        o0.w = h2u(__floats2half2_rn(v2.z, v2.w));   // 10,11
        o1.x = h2u(__floats2half2_rn(v1.x, v1.y));   // 4,5
        o1.y = h2u(__floats2half2_rn(v3.x, v3.y));   // 12,13
        o1.z = h2u(__floats2half2_rn(v1.z, v1.w));   // 6,7
        o1.w = h2u(__floats2half2_rn(v3.z, v3.w));   // 14,15
        uint4* dst = (uint4*)(out + (size_t)i * 16);
        dst[0] = o0; dst[1] = o1;
    }
}

// ============================================================
// FP16 mma GEMM on pre-permuted operands.
// C[M,N] = A[M,K] @ W[N,K]^T + bias (+res)(relu)(fp16-perm out)
// Block 128x128, BK=32 (two k16 groups), 8 warps (2x4), warp 64x32.
// Smem rows of 32 fp16 (64B); 32B-group XOR swizzle by (row>>1)&1.
// 3-stage cp.async ring, 2 CTAs/SM.
// ============================================================
#define BK 32
#define NSLOT 3
#define STAGE_B 16384                      // (128+128) rows * 64 B
#define GEMM_SMEM (NSLOT * STAGE_B)        // 49152

template<bool RELU, bool RES, bool PERM>
__global__ void __launch_bounds__(256, 2) gemm_h(
    const __half* __restrict__ A, const __half* __restrict__ W,
    const float* __restrict__ bias, const float* __restrict__ res,
    void* __restrict__ Cv, int M, int N, int K)
{
    extern __shared__ char smem[];
    const uint32_t sbase = (uint32_t)__cvta_generic_to_shared(smem);

    const int tid = threadIdx.x;
    const int lane = tid & 31, wid = tid >> 5;
    const int bm = blockIdx.y * 128, bn = blockIdx.x * 128;
    const int wm = (wid >> 2) * 64;
    const int wn = (wid & 3) * 32;
    const int gid = lane >> 2, tig = lane & 3;
    const int kap = (gid >> 1) & 1;
    const int T = K / BK;

    float acc[4][4][4];
#pragma unroll
    for (int mi = 0; mi < 4; mi++)
#pragma unroll
        for (int ni = 0; ni < 4; ni++)
#pragma unroll
            for (int r = 0; r < 4; r++) acc[mi][ni][r] = 0.f;

    auto load_tile = [&](int t, int slot) {
        const uint32_t st = sbase + (uint32_t)slot * STAGE_B;
        const int kt = t * BK;
        // A: 128 rows x 64B = 512 chunks of 16B; 2 per thread
#pragma unroll
        for (int i = 0; i < 2; i++) {
            int c = tid + i * 256;
            int r = c >> 2, h = c & 3, g = h >> 1;
            uint32_t dst = st + (uint32_t)(r * 64 + ((g ^ ((r >> 1) & 1)) * 32) + (h & 1) * 16);
            cp_async16(dst, A + (size_t)(bm + r) * K + kt + h * 8);
        }
        const uint32_t stb = st + 8192;
#pragma unroll
        for (int i = 0; i < 2; i++) {
            int c = tid + i * 256;
            int r = c >> 2, h = c & 3, g = h >> 1;
            uint32_t dst = stb + (uint32_t)(r * 64 + ((g ^ ((r >> 1) & 1)) * 32) + (h & 1) * 16);
            cp_async16(dst, W + (size_t)(bn + r) * K + kt + h * 8);
        }
    };

    load_tile(0, 0); cp_commit();
    load_tile(1, 1); cp_commit();

    int sl = 0, sl_ld = 2;
    for (int t = 0; t < T; t++) {
        if (t + 2 < T) load_tile(t + 2, sl_ld);
        cp_commit();
        cp_wait<2>();
        __syncthreads();

        const __half* Ah = (const __half*)(smem + (size_t)sl * STAGE_B);
        const __half* Bh = Ah + 128 * 32;
#pragma unroll
        for (int grp = 0; grp < 2; grp++) {
            const int off = ((grp ^ kap) * 16) + tig * 4;
            uint2 fa[4][2];
#pragma unroll
            for (int mi = 0; mi < 4; mi++) {
                const int r = wm + mi * 16 + gid;
                fa[mi][0] = *(const uint2*)(Ah + r * 32 + off);
                fa[mi][1] = *(const uint2*)(Ah + (r + 8) * 32 + off);
            }
            uint2 fb[4];
#pragma unroll
            for (int ni = 0; ni < 4; ni++)
                fb[ni] = *(const uint2*)(Bh + (wn + ni * 8 + gid) * 32 + off);
#pragma unroll
            for (int mi = 0; mi < 4; mi++)
#pragma unroll
                for (int ni = 0; ni < 4; ni++)
                    mma16h(acc[mi][ni],
                           fa[mi][0].x, fa[mi][1].x, fa[mi][0].y, fa[mi][1].y,
                           fb[ni].x, fb[ni].y);
        }
        __syncthreads();
        sl    = (sl    == 2) ? 0 : sl + 1;
        sl_ld = (sl_ld == 2) ? 0 : sl_ld + 1;
    }

    // epilogue
#pragma unroll
    for (int ni = 0; ni < 4; ni++) {
        const int cb = bn + wn + ni * 8;
        const int c0 = 2 * tig, c1 = 2 * tig + 1;
        const float b0 = bias[cb + c0], b1 = bias[cb + c1];
#pragma unroll
        for (int mi = 0; mi < 4; mi++) {
            const int row = bm + wm + mi * 16 + gid;
#pragma unroll
            for (int rr = 0; rr < 2; rr++) {
                const int r = row + rr * 8;
                float v0 = acc[mi][ni][rr * 2 + 0] + b0;
                float v1 = acc[mi][ni][rr * 2 + 1] + b1;
                size_t off = (size_t)r * N + cb + c0;
                if (RES) { v0 += res[off]; v1 += res[off + 1]; }
                if (RELU) { v0 = fmaxf(v0, 0.f); v1 = fmaxf(v1, 0.f); }
                if (PERM) {
                    __half* C16 = (__half*)Cv;
                    int g0 = cb + c0, g1 = cb + c1;
                    C16[(size_t)r * N + (g0 & ~15) + p16(g0 & 15)] = __float2half_rn(v0);
                    C16[(size_t)r * N + (g1 & ~15) + p16(g1 & 15)] = __float2half_rn(v1);
                } else {
                    float2 o; o.x = v0; o.y = v1;
                    *(float2*)&((float*)Cv)[off] = o;
                }
            }
        }
    }
}

// ============================================================
// Tensor-core causal flash attention (tf32 mma, unchanged internals).
// Output written fp16 + 16-group permuted for the Wo GEMM.
// ============================================================
#define AQ 128
#define ATTN_SMEM ((128*64 + 32*64 + 64*32 + 128*32) * 4)   // 65536 B

__global__ void __launch_bounds__(256) attn_tc(
    const float* __restrict__ qkv, __half* __restrict__ O)
{
    extern __shared__ float sm[];
    float* Qs = sm;                    // [128][64]
    float* Ks = sm + 128 * 64;         // [32][64]
    float* Vt = Ks + 32 * 64;          // [64][32]
    float* Ps = Vt + 64 * 32;          // [128][32]

    const int qi = blockIdx.x, h = blockIdx.y, b = blockIdx.z;
    const int tid = threadIdx.x, lane = tid & 31, wid = tid >> 5;
    const int gid = lane >> 2, tig = lane & 3;
    const size_t qbase = (size_t)b * LL * 3 * DD + (size_t)h * DHD;

#pragma unroll
    for (int i = 0; i < 8; i++) {
        int f = i * 256 + tid;
        int r = f >> 4, d4 = (f & 15) * 4;
        float4 v = *(const float4*)&qkv[qbase + (size_t)(qi * AQ + r) * 3072 + d4];
        float e[4] = {v.x, v.y, v.z, v.w};
        int g = d4 >> 3;
        float* qrow = Qs + r * 64 + ((g ^ (r & 3)) * 8);
#pragma unroll
        for (int ee = 0; ee < 4; ee++) {
            int d = d4 + ee;
            qrow[pidx8(d & 7)] = rnatf32(e[ee]);
        }
    }

    float m0 = -1e30f, m1 = -1e30f, l0 = 0.f, l1 = 0.f;
    float oacc[8][4];
#pragma unroll
    for (int ni = 0; ni < 8; ni++)
#pragma unroll
        for (int c = 0; c < 4; c++) oacc[ni][c] = 0.f;

    const int r0 = 16 * wid + gid;
    const int rowg0 = qi * AQ + r0;
    const int rowg1 = rowg0 + 8;
    const int xr = gid & 3;

    const int ktmax = 4 * qi + 3;
    for (int kt = 0; kt <= ktmax; kt++) {
        __syncthreads();
#pragma unroll
        for (int i = 0; i < 2; i++) {
            int f = i * 256 + tid;
            int r = f >> 4, d4 = (f & 15) * 4;
            size_t grow = qbase + (size_t)(kt * 32 + r) * 3072 + d4;
            float4 kv = *(const float4*)&qkv[grow + 1024];
            float4 vv = *(const float4*)&qkv[grow + 2048];
            float ke[4] = {kv.x, kv.y, kv.z, kv.w};
            float ve[4] = {vv.x, vv.y, vv.z, vv.w};
            int g = d4 >> 3;
            float* krow = Ks + r * 64 + ((g ^ (r & 3)) * 8);
            int sg = r >> 3, sp = pidx8(r & 7);
#pragma unroll
            for (int ee = 0; ee < 4; ee++) {
                int d = d4 + ee;
                krow[pidx8(d & 7)] = rnatf32(ke[ee]);
                Vt[d * 32 + ((sg ^ (d & 3)) * 8) + sp] = rnatf32(ve[ee]);
            }
        }
        __syncthreads();

        float sfr[4][4];
#pragma unroll
        for (int ni = 0; ni < 4; ni++)
#pragma unroll
            for (int c = 0; c < 4; c++) sfr[ni][c] = 0.f;
#pragma unroll
        for (int ks = 0; ks < 8; ks++) {
            const int sw = (ks ^ xr) * 8 + tig * 2;
            const float* pa = Qs + r0 * 64 + sw;
            float2 a02 = *(const float2*)pa;
            float2 a13 = *(const float2*)(pa + 8 * 64);
#pragma unroll
            for (int ni = 0; ni < 4; ni++) {
                float2 bb = *(const float2*)(Ks + (8 * ni + gid) * 64 + sw);
                mma8(sfr[ni],
                     __float_as_uint(a02.x), __float_as_uint(a13.x),
                     __float_as_uint(a02.y), __float_as_uint(a13.y),
                     __float_as_uint(bb.x), __float_as_uint(bb.y));
            }
        }

        const bool domask = (kt >= 4 * qi);
        const int colbase = kt * 32;
        float p[4][4];
#pragma unroll
        for (int ni = 0; ni < 4; ni++)
#pragma unroll
            for (int c = 0; c < 4; c++) {
                float v = sfr[ni][c] * 0.125f;
                if (domask) {
                    int col = colbase + 8 * ni + 2 * tig + (c & 1);
                    int rg = (c < 2) ? rowg0 : rowg1;
                    if (col > rg) v = -1e30f;
                }
                p[ni][c] = v;
            }
#pragma unroll
        for (int half = 0; half < 2; half++) {
            float rmax = -1e30f;
#pragma unroll
            for (int ni = 0; ni < 4; ni++) {
                rmax = fmaxf(rmax, p[ni][half * 2]);
                rmax = fmaxf(rmax, p[ni][half * 2 + 1]);
            }
            rmax = fmaxf(rmax, __shfl_xor_sync(0xffffffffu, rmax, 1));
            rmax = fmaxf(rmax, __shfl_xor_sync(0xffffffffu, rmax, 2));
            float mprev = half ? m1 : m0;
            float mn = fmaxf(mprev, rmax);
            float alpha = __expf(mprev - mn);
            float psum = 0.f;
#pragma unroll
            for (int ni = 0; ni < 4; ni++) {
#pragma unroll
                for (int j = 0; j < 2; j++) {
                    float e = __expf(p[ni][half * 2 + j] - mn);
                    p[ni][half * 2 + j] = e;
                    psum += e;
                }
            }
            psum += __shfl_xor_sync(0xffffffffu, psum, 1);
            psum += __shfl_xor_sync(0xffffffffu, psum, 2);
            if (half == 0) { l0 = l0 * alpha + psum; m0 = mn; }
            else           { l1 = l1 * alpha + psum; m1 = mn; }
#pragma unroll
            for (int ni = 0; ni < 8; ni++) {
                oacc[ni][half * 2]     *= alpha;
                oacc[ni][half * 2 + 1] *= alpha;
            }
        }
#pragma unroll
        for (int ni = 0; ni < 4; ni++) {
            float* prow0 = Ps + r0 * 32 + ((ni ^ xr) * 8);
            float* prow1 = prow0 + 8 * 32;
#pragma unroll
            for (int j = 0; j < 2; j++) {
                int pos = pidx8(2 * tig + j);
                prow0[pos] = rnatf32(p[ni][j]);
                prow1[pos] = rnatf32(p[ni][2 + j]);
            }
        }
        __syncwarp();

#pragma unroll
        for (int ksp = 0; ksp < 4; ksp++) {
            const int swp = (ksp ^ xr) * 8 + tig * 2;
            const float* pa = Ps + r0 * 32 + swp;
            float2 a02 = *(const float2*)pa;
            float2 a13 = *(const float2*)(pa + 8 * 32);
#pragma unroll
            for (int ni = 0; ni < 8; ni++) {
                const int d = 8 * ni + gid;
                float2 bb = *(const float2*)(Vt + d * 32 + ((ksp ^ (d & 3)) * 8) + tig * 2);
                mma8(oacc[ni],
                     __float_as_uint(a02.x), __float_as_uint(a13.x),
                     __float_as_uint(a02.y), __float_as_uint(a13.y),
                     __float_as_uint(bb.x), __float_as_uint(bb.y));
            }
        }
    }

    // write O fp16, 16-group permuted (dh-groups; h*64 is 16-aligned)
    float inv0 = 1.0f / l0, inv1 = 1.0f / l1;
    size_t ob0 = ((size_t)(b * LL + rowg0) * HH + h) * DHD;
    size_t ob1 = ((size_t)(b * LL + rowg1) * HH + h) * DHD;
#pragma unroll
    for (int ni = 0; ni < 8; ni++) {
#pragma unroll
        for (int j = 0; j < 2; j++) {
            int dcol = 8 * ni + 2 * tig + j;
            int pos = (dcol & ~15) + p16(dcol & 15);
            O[ob0 + pos] = __float2half_rn(oacc[ni][j] * inv0);
            O[ob1 + pos] = __float2half_rn(oacc[ni][2 + j] * inv1);
        }
    }
}

// ============================================================
// LayerNorm (ddof=1, (std+eps)); optional fp16-permuted 2nd output
// ============================================================
__global__ void __launch_bounds__(256) ln_kernel(
    const float* __restrict__ X, const float* __restrict__ gamma,
    const float* __restrict__ beta, float* __restrict__ Y,
    __half* __restrict__ Yr)
{
    const int row = blockIdx.x;
    const int tid = threadIdx.x;
    const int lane = tid & 31, wid = tid >> 5;
    __shared__ float red[8];

    float4 v = *(const float4*)&X[(size_t)row * DD + tid * 4];

    float s = v.x + v.y + v.z + v.w;
#pragma unroll
    for (int off = 16; off > 0; off >>= 1) s += __shfl_xor_sync(0xffffffffu, s, off);
    if (lane == 0) red[wid] = s;
    __syncthreads();
    float mean = 0.f;
#pragma unroll
    for (int i = 0; i < 8; i++) mean += red[i];
    mean *= (1.0f / 1024.f);
    __syncthreads();

    float dx = v.x - mean, dy = v.y - mean, dz = v.z - mean, dw = v.w - mean;
    float ss = dx*dx + dy*dy + dz*dz + dw*dw;
#pragma unroll
    for (int off = 16; off > 0; off >>= 1) ss += __shfl_xor_sync(0xffffffffu, ss, off);
    if (lane == 0) red[wid] = ss;
    __syncthreads();
    float var = 0.f;
#pragma unroll
    for (int i = 0; i < 8; i++) var += red[i];
    var *= (1.0f / 1023.f);
    float istd = 1.0f / (sqrtf(var) + 1e-6f);

    float4 g  = *(const float4*)&gamma[tid * 4];
    float4 bb = *(const float4*)&beta[tid * 4];
    float o[4];
    o[0] = dx * istd * g.x + bb.x;
    o[1] = dy * istd * g.y + bb.y;
    o[2] = dz * istd * g.z + bb.z;
    o[3] = dw * istd * g.w + bb.w;
    float4 outv; outv.x = o[0]; outv.y = o[1]; outv.z = o[2]; outv.w = o[3];
    *(float4*)&Y[(size_t)row * DD + tid * 4] = outv;
    if (Yr) {
        __half* yr = Yr + (size_t)row * DD;
#pragma unroll
        for (int e = 0; e < 4; e++) {
            int col = tid * 4 + e;
            yr[(col & ~15) + p16(col & 15)] = __float2half_rn(o[e]);
        }
    }
}

// ============================================================
extern "C" void kernel_launch(void* const* d_in, const int* in_sizes, int n_in,
                              void* d_out, int out_size)
{
    const float* x     = (const float*)d_in[0];
    const float* Wqkv  = (const float*)d_in[2];
    const float* bqkv  = (const float*)d_in[3];
    const float* Wo    = (const float*)d_in[4];
    const float* bo    = (const float*)d_in[5];
    const float* ln1_a = (const float*)d_in[6];
    const float* ln1_b = (const float*)d_in[7];
    const float* W1    = (const float*)d_in[8];
    const float* b1    = (const float*)d_in[9];
    const float* W2    = (const float*)d_in[10];
    const float* b2    = (const float*)d_in[11];
    const float* ln2_a = (const float*)d_in[12];
    const float* ln2_b = (const float*)d_in[13];
    float* out = (float*)d_out;

    float  *qkv, *t0, *h1;
    __half *attn, *h1r, *ffn, *xr, *wqkvr, *wor, *w1r, *w2r;
    cudaGetSymbolAddress((void**)&qkv,   g_qkv);
    cudaGetSymbolAddress((void**)&attn,  g_attn);
    cudaGetSymbolAddress((void**)&t0,    g_t0);
    cudaGetSymbolAddress((void**)&h1,    g_h1);
    cudaGetSymbolAddress((void**)&h1r,   g_h1r);
    cudaGetSymbolAddress((void**)&ffn,   g_ffn);
    cudaGetSymbolAddress((void**)&xr,    g_xr);
    cudaGetSymbolAddress((void**)&wqkvr, g_wqkvr);
    cudaGetSymbolAddress((void**)&wor,   g_wor);
    cudaGetSymbolAddress((void**)&w1r,   g_w1r);
    cudaGetSymbolAddress((void**)&w2r,   g_w2r);

    cudaFuncSetAttribute(gemm_h<false,false,false>, cudaFuncAttributeMaxDynamicSharedMemorySize, GEMM_SMEM);
    cudaFuncSetAttribute(gemm_h<true ,false,true >, cudaFuncAttributeMaxDynamicSharedMemorySize, GEMM_SMEM);
    cudaFuncSetAttribute(gemm_h<false,true ,false>, cudaFuncAttributeMaxDynamicSharedMemorySize, GEMM_SMEM);
    cudaFuncSetAttribute(attn_tc, cudaFuncAttributeMaxDynamicSharedMemorySize, ATTN_SMEM);

    dim3 blk(256);

    // convert+permute all GEMM A/B operands to fp16 16-groups
    round_perm16<<<(MTOT*DD/16 + 255)/256, blk>>>(x, xr, MTOT*DD/16);
    round_perm16<<<(3*DD*DD/16 + 255)/256, blk>>>(Wqkv, wqkvr, 3*DD*DD/16);
    round_perm16<<<(DD*DD/16 + 255)/256, blk>>>(Wo, wor, DD*DD/16);
    round_perm16<<<(DFFN*DD/16 + 255)/256, blk>>>(W1, w1r, DFFN*DD/16);
    round_perm16<<<(DD*DFFN/16 + 255)/256, blk>>>(W2, w2r, DD*DFFN/16);

    // 1) qkv = x @ Wqkv^T + bqkv (fp32 out)       [4096 x 3072] K=1024
    gemm_h<false,false,false><<<dim3(3072/128, MTOT/128), blk, GEMM_SMEM>>>(
        xr, wqkvr, bqkv, nullptr, qkv, MTOT, 3*DD, DD);

    // 2) tensor-core causal flash attention -> attn (fp16 perm)
    attn_tc<<<dim3(LL/AQ, HH, BBAT), blk, ATTN_SMEM>>>(qkv, attn);

    // 3) t0 = attn @ Wo^T + bo + x (fp32 out)
    gemm_h<false,true,false><<<dim3(DD/128, MTOT/128), blk, GEMM_SMEM>>>(
        attn, wor, bo, x, t0, MTOT, DD, DD);

    // 4) h1 = LN1(t0) fp32, h1r fp16 perm
    ln_kernel<<<MTOT, blk>>>(t0, ln1_a, ln1_b, h1, h1r);

    // 5) ffn = relu(h1r @ W1^T + b1) (fp16 perm out)   [4096 x 4096]
    gemm_h<true,false,true><<<dim3(DFFN/128, MTOT/128), blk, GEMM_SMEM>>>(
        h1r, w1r, b1, nullptr, ffn, MTOT, DFFN, DD);

    // 6) t0 = ffn @ W2^T + b2 + h1 (fp32 out)     [4096 x 1024] K=4096
    gemm_h<false,true,false><<<dim3(DD/128, MTOT/128), blk, GEMM_SMEM>>>(
        ffn, w2r, b2, h1, t0, MTOT, DD, DFFN);

    // 7) out = LN2(t0)
    ln_kernel<<<MTOT, blk>>>(t0, ln2_a, ln2_b, out, nullptr);
}

// round 11
// speedup vs baseline: 4.5749x; 1.4831x over previous
#include <cuda_runtime.h>
#include <cuda_fp16.h>
#include <cstdint>
#include <math.h>

#define BBAT 2
#define LL   2048
#define DD   1024
#define HH   16
#define DHD  64
#define DFFN 4096
#define MTOT (BBAT*LL)   // 4096

// ---- scratch (__device__ globals; no allocation allowed) ----
__device__ __half g_qk  [(size_t)MTOT*2*DD];          // Q|K fp16 perm16
__device__ __half g_vt  [(size_t)BBAT*HH*DHD*LL];     // V^T fp16 perm16(l)
__device__ __half g_attn[(size_t)MTOT*DD];
__device__ float  g_t0  [(size_t)MTOT*DD];
__device__ float  g_h1  [(size_t)MTOT*DD];
__device__ __half g_h1r [(size_t)MTOT*DD];
__device__ __half g_ffn [(size_t)MTOT*DFFN];
__device__ __half g_xr  [(size_t)MTOT*DD];
__device__ __half g_wqkvr[(size_t)3*DD*DD];
__device__ __half g_wor [(size_t)DD*DD];
__device__ __half g_w1r [(size_t)DFFN*DD];
__device__ __half g_w2r [(size_t)DD*DFFN];

// ============================================================
// Helpers
// ============================================================
__device__ __forceinline__ void mma16h(float* c, uint32_t a0, uint32_t a1,
                                       uint32_t a2, uint32_t a3,
                                       uint32_t b0, uint32_t b1) {
    asm volatile(
        "mma.sync.aligned.m16n8k16.row.col.f32.f16.f16.f32 "
        "{%0,%1,%2,%3}, {%4,%5,%6,%7}, {%8,%9}, {%0,%1,%2,%3};\n"
        : "+f"(c[0]), "+f"(c[1]), "+f"(c[2]), "+f"(c[3])
        : "r"(a0), "r"(a1), "r"(a2), "r"(a3), "r"(b0), "r"(b1));
}
__device__ __forceinline__ void cp_async16(uint32_t dst, const void* src) {
    asm volatile("cp.async.cg.shared.global [%0], [%1], 16;\n" :: "r"(dst), "l"(src));
}
__device__ __forceinline__ void cp_commit() { asm volatile("cp.async.commit_group;\n"); }
template<int N> __device__ __forceinline__ void cp_wait() {
    asm volatile("cp.async.wait_group %0;\n" :: "n"(N));
}
// fp16 16-group permuted index: order [0,1,8,9,2,3,10,11,4,5,12,13,6,7,14,15]
__device__ __forceinline__ int p16(int c) {
    return ((c & 7) >> 1) * 4 + ((c >> 3) & 1) * 2 + (c & 1);
}
__device__ __forceinline__ uint32_t h2u(__half2 h) {
    return *reinterpret_cast<uint32_t*>(&h);
}

// ============================================================
// fp32 -> fp16 convert + permute into 16-groups
// ============================================================
__global__ void __launch_bounds__(256) round_perm16(
    const float* __restrict__ in, __half* __restrict__ out, int n16)
{
    int i = blockIdx.x * 256 + threadIdx.x;
    if (i < n16) {
        const float4* src = (const float4*)(in + (size_t)i * 16);
        float4 v0 = src[0], v1 = src[1], v2 = src[2], v3 = src[3];
        uint4 o0, o1;
        o0.x = h2u(__floats2half2_rn(v0.x, v0.y));
        o0.y = h2u(__floats2half2_rn(v2.x, v2.y));
        o0.z = h2u(__floats2half2_rn(v0.z, v0.w));
        o0.w = h2u(__floats2half2_rn(v2.z, v2.w));
        o1.x = h2u(__floats2half2_rn(v1.x, v1.y));
        o1.y = h2u(__floats2half2_rn(v3.x, v3.y));
        o1.z = h2u(__floats2half2_rn(v1.z, v1.w));
        o1.w = h2u(__floats2half2_rn(v3.z, v3.w));
        uint4* dst = (uint4*)(out + (size_t)i * 16);
        dst[0] = o0; dst[1] = o1;
    }
}

// ============================================================
// FP16 mma GEMM on pre-permuted operands.
// OUT: 0 = fp32, 1 = fp16 perm16, 2 = QKV split (Q/K perm16 + V^T)
// Block 128x128, BK=32, 8 warps (2x4), warp 64x32.
// 4-slot cp.async ring, lookahead 3, ONE syncthreads per tile.
// ============================================================
#define BK 32
#define NSLOT 4
#define STAGE_B 16384
#define GEMM_SMEM (NSLOT * STAGE_B)        // 65536

template<bool RELU, bool RES, int OUT>
__global__ void __launch_bounds__(256, 2) gemm_h(
    const __half* __restrict__ A, const __half* __restrict__ W,
    const float* __restrict__ bias, const float* __restrict__ res,
    void* __restrict__ Cv, __half* __restrict__ QKo, __half* __restrict__ VTo,
    int M, int N, int K)
{
    extern __shared__ char smem[];
    const uint32_t sbase = (uint32_t)__cvta_generic_to_shared(smem);

    const int tid = threadIdx.x;
    const int lane = tid & 31, wid = tid >> 5;
    const int bm = blockIdx.y * 128, bn = blockIdx.x * 128;
    const int wm = (wid >> 2) * 64;
    const int wn = (wid & 3) * 32;
    const int gid = lane >> 2, tig = lane & 3;
    const int kap = (gid >> 1) & 1;
    const int T = K / BK;

    float acc[4][4][4];
#pragma unroll
    for (int mi = 0; mi < 4; mi++)
#pragma unroll
        for (int ni = 0; ni < 4; ni++)
#pragma unroll
            for (int r = 0; r < 4; r++) acc[mi][ni][r] = 0.f;

    auto load_tile = [&](int t, int slot) {
        const uint32_t st = sbase + (uint32_t)slot * STAGE_B;
        const int kt = t * BK;
#pragma unroll
        for (int i = 0; i < 2; i++) {
            int c = tid + i * 256;
            int r = c >> 2, h = c & 3, g = h >> 1;
            uint32_t dst = st + (uint32_t)(r * 64 + ((g ^ ((r >> 1) & 1)) * 32) + (h & 1) * 16);
            cp_async16(dst, A + (size_t)(bm + r) * K + kt + h * 8);
        }
        const uint32_t stb = st + 8192;
#pragma unroll
        for (int i = 0; i < 2; i++) {
            int c = tid + i * 256;
            int r = c >> 2, h = c & 3, g = h >> 1;
            uint32_t dst = stb + (uint32_t)(r * 64 + ((g ^ ((r >> 1) & 1)) * 32) + (h & 1) * 16);
            cp_async16(dst, W + (size_t)(bn + r) * K + kt + h * 8);
        }
    };

    load_tile(0, 0); cp_commit();
    load_tile(1, 1); cp_commit();
    load_tile(2, 2); cp_commit();

    for (int t = 0; t < T; t++) {
        cp_wait<2>();
        __syncthreads();
        if (t + 3 < T) load_tile(t + 3, (t + 3) & 3);
        cp_commit();

        const __half* Ah = (const __half*)(smem + (size_t)(t & 3) * STAGE_B);
        const __half* Bh = Ah + 128 * 32;
#pragma unroll
        for (int grp = 0; grp < 2; grp++) {
            const int off = ((grp ^ kap) * 16) + tig * 4;
            uint2 fa[4][2];
#pragma unroll
            for (int mi = 0; mi < 4; mi++) {
                const int r = wm + mi * 16 + gid;
                fa[mi][0] = *(const uint2*)(Ah + r * 32 + off);
                fa[mi][1] = *(const uint2*)(Ah + (r + 8) * 32 + off);
            }
            uint2 fb[4];
#pragma unroll
            for (int ni = 0; ni < 4; ni++)
                fb[ni] = *(const uint2*)(Bh + (wn + ni * 8 + gid) * 32 + off);
#pragma unroll
            for (int mi = 0; mi < 4; mi++)
#pragma unroll
                for (int ni = 0; ni < 4; ni++)
                    mma16h(acc[mi][ni],
                           fa[mi][0].x, fa[mi][1].x, fa[mi][0].y, fa[mi][1].y,
                           fb[ni].x, fb[ni].y);
        }
        __syncthreads();   // readers done before slot (t+4)&3==t&3 reload next iter
    }

    // epilogue
#pragma unroll
    for (int ni = 0; ni < 4; ni++) {
        const int cb = bn + wn + ni * 8;
        const int c0 = 2 * tig, c1 = 2 * tig + 1;
        const float b0 = bias[cb + c0], b1 = bias[cb + c1];
#pragma unroll
        for (int mi = 0; mi < 4; mi++) {
            const int row = bm + wm + mi * 16 + gid;
#pragma unroll
            for (int rr = 0; rr < 2; rr++) {
                const int r = row + rr * 8;
                float v0 = acc[mi][ni][rr * 2 + 0] + b0;
                float v1 = acc[mi][ni][rr * 2 + 1] + b1;
                size_t off = (size_t)r * N + cb + c0;
                if (RES) { v0 += res[off]; v1 += res[off + 1]; }
                if (RELU) { v0 = fmaxf(v0, 0.f); v1 = fmaxf(v1, 0.f); }
                if (OUT == 0) {
                    float2 o; o.x = v0; o.y = v1;
                    *(float2*)&((float*)Cv)[off] = o;
                } else if (OUT == 1) {
                    __half* C16 = (__half*)Cv;
                    int col0 = cb + c0;
                    size_t idx = (size_t)r * N + (col0 & ~15) + p16(col0 & 15);
                    *(__half2*)&C16[idx] = __floats2half2_rn(v0, v1);
                } else {
                    // QKV split: cols [0,2048) -> QK perm16; [2048,3072) -> V^T
                    int col0 = cb + c0;
                    __half h0 = __float2half_rn(v0), h1v = __float2half_rn(v1);
                    if (col0 < 2048) {
                        size_t idx = (size_t)r * 2048 + (col0 & ~15) + p16(col0 & 15);
                        *(__half2*)&QKo[idx] = __halves2half2(h0, h1v);
                    } else {
                        int d0 = col0 - 2048;
                        int hd = d0 >> 6, dh = d0 & 63;
                        int b_ = r >> 11, l = r & 2047;
                        size_t lidx = (size_t)(l & ~15) + p16(l & 15);
                        size_t rowb = ((size_t)(b_ * HH + hd) * DHD + dh) * LL;
                        VTo[rowb + lidx]      = h0;
                        VTo[rowb + LL + lidx] = h1v;   // dh+1 (dh even)
                    }
                }
            }
        }
    }
}

// ============================================================
// FP16 tensor-core causal flash attention.
// Q/K from g_qk (perm16), V^T from g_vt (perm16 in l). All mma fp16.
// BQ=128, BK=32 keys/tile, 8 warps (warp = 16 q-rows). cp.async
// double-buffered K/V. Output fp16 perm16 for the Wo GEMM.
// ============================================================
#define AQ 128

__global__ void __launch_bounds__(256) attn_h(
    const __half* __restrict__ qk, const __half* __restrict__ vt,
    __half* __restrict__ O)
{
    __shared__ __half Qs[128 * 64];       // 16KB, 128B rows (d=64)
    __shared__ __half Ks[2][32 * 64];     // 8KB, 128B rows
    __shared__ __half Vts[2][64 * 32];    // 8KB, 64B rows (k=32)
    __shared__ __half Ps[128 * 32];       // 8KB, 64B rows

    const int qi = blockIdx.x, h = blockIdx.y, b = blockIdx.z;
    const int tid = threadIdx.x, lane = tid & 31, wid = tid >> 5;
    const int gid = lane >> 2, tig = lane & 3;

    const uint32_t sQ = (uint32_t)__cvta_generic_to_shared(Qs);
    const uint32_t sK = (uint32_t)__cvta_generic_to_shared(Ks);
    const uint32_t sV = (uint32_t)__cvta_generic_to_shared(Vts);

    const __half* qbQ = qk + ((size_t)(b * LL + qi * AQ)) * 2048 + h * 64;
    const __half* qbK = qk + ((size_t)(b * LL)) * 2048 + 1024 + h * 64;
    const __half* vb  = vt + ((size_t)(b * HH + h) * DHD) * LL;

    // Q fill: 128 rows x 8 chunks(16B); group g=ch>>1 at (g ^ (r&3))*32B
#pragma unroll
    for (int i = 0; i < 4; i++) {
        int c = tid + i * 256;
        int r = c >> 3, ch = c & 7;
        uint32_t dst = sQ + (uint32_t)(r * 128 + (((ch >> 1) ^ (r & 3)) * 32) + (ch & 1) * 16);
        cp_async16(dst, qbQ + (size_t)r * 2048 + ch * 8);
    }
    auto load_kv = [&](int kt, int slot) {
        {   // K: 32 rows x 8 chunks
            int r = tid >> 3, ch = tid & 7;
            uint32_t dst = sK + (uint32_t)(slot * 4096 + r * 128 + (((ch >> 1) ^ (r & 3)) * 32) + (ch & 1) * 16);
            cp_async16(dst, qbK + (size_t)(kt * 32 + r) * 2048 + ch * 8);
        }
        {   // V^T: 64 d-rows x 4 chunks
            int d = tid >> 2, ch = tid & 3;
            uint32_t dst = sV + (uint32_t)(slot * 4096 + d * 64 + (((ch >> 1) ^ ((d >> 1) & 1)) * 32) + (ch & 1) * 16);
            cp_async16(dst, vb + (size_t)d * LL + kt * 32 + ch * 8);
        }
    };
    load_kv(0, 0); cp_commit();

    float m0 = -1e30f, m1 = -1e30f, l0 = 0.f, l1 = 0.f;
    float oacc[8][4];
#pragma unroll
    for (int ni = 0; ni < 8; ni++)
#pragma unroll
        for (int c = 0; c < 4; c++) oacc[ni][c] = 0.f;

    const int r0 = 16 * wid + gid;
    const int rowg0 = qi * AQ + r0, rowg1 = rowg0 + 8;
    const int keyQ = r0 & 3;
    const int keyP = (r0 >> 1) & 1;
    const int ktmax = 4 * qi + 3;

    for (int kt = 0; kt <= ktmax; kt++) {
        cp_wait<0>();
        __syncthreads();
        if (kt + 1 <= ktmax) load_kv(kt + 1, (kt + 1) & 1);
        cp_commit();

        const __half* Kt  = Ks[kt & 1];
        const __half* Vtt = Vts[kt & 1];

        // ---- S = Q K^T : 16x32 per warp, 4 d-groups ----
        float sfr[4][4];
#pragma unroll
        for (int ni = 0; ni < 4; ni++)
#pragma unroll
            for (int c = 0; c < 4; c++) sfr[ni][c] = 0.f;
#pragma unroll
        for (int grp = 0; grp < 4; grp++) {
            const __half* qa = Qs + r0 * 64 + ((grp ^ keyQ) * 16) + tig * 4;
            uint2 fa0 = *(const uint2*)qa;
            uint2 fa1 = *(const uint2*)(qa + 8 * 64);
#pragma unroll
            for (int ni = 0; ni < 4; ni++) {
                int kk = 8 * ni + gid;
                uint2 fb = *(const uint2*)(Kt + kk * 64 + ((grp ^ (kk & 3)) * 16) + tig * 4);
                mma16h(sfr[ni], fa0.x, fa1.x, fa0.y, fa1.y, fb.x, fb.y);
            }
        }

        // ---- scale, mask, online softmax ----
        const bool domask = (kt >= 4 * qi);
        const int colbase = kt * 32;
        float p[4][4];
#pragma unroll
        for (int ni = 0; ni < 4; ni++)
#pragma unroll
            for (int c = 0; c < 4; c++) {
                float v = sfr[ni][c] * 0.125f;
                if (domask) {
                    int col = colbase + 8 * ni + 2 * tig + (c & 1);
                    int rg = (c < 2) ? rowg0 : rowg1;
                    if (col > rg) v = -1e30f;
                }
                p[ni][c] = v;
            }
#pragma unroll
        for (int half = 0; half < 2; half++) {
            float rmax = -1e30f;
#pragma unroll
            for (int ni = 0; ni < 4; ni++) {
                rmax = fmaxf(rmax, p[ni][half * 2]);
                rmax = fmaxf(rmax, p[ni][half * 2 + 1]);
            }
            rmax = fmaxf(rmax, __shfl_xor_sync(0xffffffffu, rmax, 1));
            rmax = fmaxf(rmax, __shfl_xor_sync(0xffffffffu, rmax, 2));
            float mprev = half ? m1 : m0;
            float mn = fmaxf(mprev, rmax);
            float alpha = __expf(mprev - mn);
            float psum = 0.f;
#pragma unroll
            for (int ni = 0; ni < 4; ni++) {
#pragma unroll
                for (int j = 0; j < 2; j++) {
                    float e = __expf(p[ni][half * 2 + j] - mn);
                    p[ni][half * 2 + j] = e;
                    psum += e;
                }
            }
            psum += __shfl_xor_sync(0xffffffffu, psum, 1);
            psum += __shfl_xor_sync(0xffffffffu, psum, 2);
            if (half == 0) { l0 = l0 * alpha + psum; m0 = mn; }
            else           { l1 = l1 * alpha + psum; m1 = mn; }
#pragma unroll
            for (int ni = 0; ni < 8; ni++) {
                oacc[ni][half * 2]     *= alpha;
                oacc[ni][half * 2 + 1] *= alpha;
            }
        }

        // ---- write P fp16 perm16 to Ps ----
#pragma unroll
        for (int ni = 0; ni < 4; ni++) {
            int g16 = ni >> 1;
            int off0 = r0 * 32 + ((g16 ^ keyP) * 16) + 4 * tig + 2 * (ni & 1);
            *(__half2*)(Ps + off0)          = __floats2half2_rn(p[ni][0], p[ni][1]);
            *(__half2*)(Ps + off0 + 8 * 32) = __floats2half2_rn(p[ni][2], p[ni][3]);
        }
        __syncwarp();

        // ---- O += P V (B = V^T rows d) ----
#pragma unroll
        for (int grp = 0; grp < 2; grp++) {
            const __half* pa = Ps + r0 * 32 + ((grp ^ keyP) * 16) + tig * 4;
            uint2 fa0 = *(const uint2*)pa;
            uint2 fa1 = *(const uint2*)(pa + 8 * 32);
#pragma unroll
            for (int ni = 0; ni < 8; ni++) {
                int dd = 8 * ni + gid;
                uint2 fb = *(const uint2*)(Vtt + dd * 32 + ((grp ^ ((dd >> 1) & 1)) * 16) + tig * 4);
                mma16h(oacc[ni], fa0.x, fa1.x, fa0.y, fa1.y, fb.x, fb.y);
            }
        }
    }

    // ---- write O fp16 perm16 ----
    float inv0 = 1.0f / l0, inv1 = 1.0f / l1;
    size_t ob0 = ((size_t)(b * LL + rowg0) * HH + h) * DHD;
    size_t ob1 = ((size_t)(b * LL + rowg1) * HH + h) * DHD;
#pragma unroll
    for (int ni = 0; ni < 8; ni++) {
        int dcol = 8 * ni + 2 * tig;
        int pos = (dcol & ~15) + p16(dcol & 15);
        *(__half2*)&O[ob0 + pos] = __floats2half2_rn(oacc[ni][0] * inv0, oacc[ni][1] * inv0);
        *(__half2*)&O[ob1 + pos] = __floats2half2_rn(oacc[ni][2] * inv1, oacc[ni][3] * inv1);
    }
}

// ============================================================
// LayerNorm (ddof=1, (std+eps)); optional fp16-permuted 2nd output
// ============================================================
__global__ void __launch_bounds__(256) ln_kernel(
    const float* __restrict__ X, const float* __restrict__ gamma,
    const float* __restrict__ beta, float* __restrict__ Y,
    __half* __restrict__ Yr)
{
    const int row = blockIdx.x;
    const int tid = threadIdx.x;
    const int lane = tid & 31, wid = tid >> 5;
    __shared__ float red[8];

    float4 v = *(const float4*)&X[(size_t)row * DD + tid * 4];

    float s = v.x + v.y + v.z + v.w;
#pragma unroll
    for (int off = 16; off > 0; off >>= 1) s += __shfl_xor_sync(0xffffffffu, s, off);
    if (lane == 0) red[wid] = s;
    __syncthreads();
    float mean = 0.f;
#pragma unroll
    for (int i = 0; i < 8; i++) mean += red[i];
    mean *= (1.0f / 1024.f);
    __syncthreads();

    float dx = v.x - mean, dy = v.y - mean, dz = v.z - mean, dw = v.w - mean;
    float ss = dx*dx + dy*dy + dz*dz + dw*dw;
#pragma unroll
    for (int off = 16; off > 0; off >>= 1) ss += __shfl_xor_sync(0xffffffffu, ss, off);
    if (lane == 0) red[wid] = ss;
    __syncthreads();
    float var = 0.f;
#pragma unroll
    for (int i = 0; i < 8; i++) var += red[i];
    var *= (1.0f / 1023.f);
    float istd = 1.0f / (sqrtf(var) + 1e-6f);

    float4 g  = *(const float4*)&gamma[tid * 4];
    float4 bb = *(const float4*)&beta[tid * 4];
    float o[4];
    o[0] = dx * istd * g.x + bb.x;
    o[1] = dy * istd * g.y + bb.y;
    o[2] = dz * istd * g.z + bb.z;
    o[3] = dw * istd * g.w + bb.w;
    float4 outv; outv.x = o[0]; outv.y = o[1]; outv.z = o[2]; outv.w = o[3];
    *(float4*)&Y[(size_t)row * DD + tid * 4] = outv;
    if (Yr) {
        __half* yr = Yr + (size_t)row * DD;
#pragma unroll
        for (int e = 0; e < 4; e++) {
            int col = tid * 4 + e;
            yr[(col & ~15) + p16(col & 15)] = __float2half_rn(o[e]);
        }
    }
}

// ============================================================
extern "C" void kernel_launch(void* const* d_in, const int* in_sizes, int n_in,
                              void* d_out, int out_size)
{
    const float* x     = (const float*)d_in[0];
    const float* Wqkv  = (const float*)d_in[2];
    const float* bqkv  = (const float*)d_in[3];
    const float* Wo    = (const float*)d_in[4];
    const float* bo    = (const float*)d_in[5];
    const float* ln1_a = (const float*)d_in[6];
    const float* ln1_b = (const float*)d_in[7];
    const float* W1    = (const float*)d_in[8];
    const float* b1    = (const float*)d_in[9];
    const float* W2    = (const float*)d_in[10];
    const float* b2    = (const float*)d_in[11];
    const float* ln2_a = (const float*)d_in[12];
    const float* ln2_b = (const float*)d_in[13];
    float* out = (float*)d_out;

    float  *t0, *h1;
    __half *qkb, *vtb, *attn, *h1r, *ffn, *xr, *wqkvr, *wor, *w1r, *w2r;
    cudaGetSymbolAddress((void**)&qkb,   g_qk);
    cudaGetSymbolAddress((void**)&vtb,   g_vt);
    cudaGetSymbolAddress((void**)&attn,  g_attn);
    cudaGetSymbolAddress((void**)&t0,    g_t0);
    cudaGetSymbolAddress((void**)&h1,    g_h1);
    cudaGetSymbolAddress((void**)&h1r,   g_h1r);
    cudaGetSymbolAddress((void**)&ffn,   g_ffn);
    cudaGetSymbolAddress((void**)&xr,    g_xr);
    cudaGetSymbolAddress((void**)&wqkvr, g_wqkvr);
    cudaGetSymbolAddress((void**)&wor,   g_wor);
    cudaGetSymbolAddress((void**)&w1r,   g_w1r);
    cudaGetSymbolAddress((void**)&w2r,   g_w2r);

    cudaFuncSetAttribute(gemm_h<false,false,2>, cudaFuncAttributeMaxDynamicSharedMemorySize, GEMM_SMEM);
    cudaFuncSetAttribute(gemm_h<false,true ,0>, cudaFuncAttributeMaxDynamicSharedMemorySize, GEMM_SMEM);
    cudaFuncSetAttribute(gemm_h<true ,false,1>, cudaFuncAttributeMaxDynamicSharedMemorySize, GEMM_SMEM);

    dim3 blk(256);

    // convert+permute all GEMM A/B operands to fp16 16-groups
    round_perm16<<<(MTOT*DD/16 + 255)/256, blk>>>(x, xr, MTOT*DD/16);
    round_perm16<<<(3*DD*DD/16 + 255)/256, blk>>>(Wqkv, wqkvr, 3*DD*DD/16);
    round_perm16<<<(DD*DD/16 + 255)/256, blk>>>(Wo, wor, DD*DD/16);
    round_perm16<<<(DFFN*DD/16 + 255)/256, blk>>>(W1, w1r, DFFN*DD/16);
    round_perm16<<<(DD*DFFN/16 + 255)/256, blk>>>(W2, w2r, DD*DFFN/16);

    // 1) QKV GEMM: Q/K -> g_qk (fp16 perm16), V -> g_vt (fp16 transposed)
    gemm_h<false,false,2><<<dim3(3072/128, MTOT/128), blk, GEMM_SMEM>>>(
        xr, wqkvr, bqkv, nullptr, nullptr, qkb, vtb, MTOT, 3*DD, DD);

    // 2) fp16 tensor-core causal flash attention -> attn (fp16 perm16)
    attn_h<<<dim3(LL/AQ, HH, BBAT), blk>>>(qkb, vtb, attn);

    // 3) t0 = attn @ Wo^T + bo + x (fp32 out)
    gemm_h<false,true,0><<<dim3(DD/128, MTOT/128), blk, GEMM_SMEM>>>(
        attn, wor, bo, x, t0, nullptr, nullptr, MTOT, DD, DD);

    // 4) h1 = LN1(t0) fp32, h1r fp16 perm16
    ln_kernel<<<MTOT, blk>>>(t0, ln1_a, ln1_b, h1, h1r);

    // 5) ffn = relu(h1r @ W1^T + b1) (fp16 perm16 out)
    gemm_h<true,false,1><<<dim3(DFFN/128, MTOT/128), blk, GEMM_SMEM>>>(
        h1r, w1r, b1, nullptr, ffn, nullptr, nullptr, MTOT, DFFN, DD);

    // 6) t0 = ffn @ W2^T + b2 + h1 (fp32 out)
    gemm_h<false,true,0><<<dim3(DD/128, MTOT/128), blk, GEMM_SMEM>>>(
        ffn, w2r, b2, h1, t0, nullptr, nullptr, MTOT, DD, DFFN);

    // 7) out = LN2(t0)
    ln_kernel<<<MTOT, blk>>>(t0, ln2_a, ln2_b, out, nullptr);
}